// round 10
// baseline (speedup 1.0000x reference)
#include <cuda_runtime.h>
#include <math.h>
#include <stdint.h>

typedef unsigned long long ull;

// output layout (float32)
#define OFF_CTC_S 0
#define OFF_LEN_S 328320
#define OFF_CTC_C 328352
#define OFF_LEN_C 656672
#define OFF_CLOSE 656704

// ---------------- scratch (device globals; no allocation) ----------------
__device__ float g_xz[2u*32u*1024u*1024u];      // xz for lstm0; reused (smaller) for lstm1
__device__ float g_pool[2*32*342*256];          // pooled lstm0 output
__device__ float g_hA[2*32*342*256];            // lstm1 pass A output
__device__ float g_hB[2*32*342*256];            // lstm1 pass B output

// ---------------- cluster / mbarrier helpers ----------------
__device__ __forceinline__ uint32_t smem_u32(const void* p) {
    uint32_t a;
    asm("{ .reg .u64 t; cvta.to.shared.u64 t, %1; cvt.u32.u64 %0, t; }" : "=r"(a) : "l"(p));
    return a;
}
__device__ __forceinline__ uint32_t mapa_rank(uint32_t addr, uint32_t rank) {
    uint32_t r;
    asm("mapa.shared::cluster.u32 %0, %1, %2;" : "=r"(r) : "r"(addr), "r"(rank));
    return r;
}
__device__ __forceinline__ void mbar_init(uint32_t addr, uint32_t count) {
    asm volatile("mbarrier.init.shared.b64 [%0], %1;" :: "r"(addr), "r"(count) : "memory");
}
__device__ __forceinline__ void mbar_expect(uint32_t addr, uint32_t tx) {
    asm volatile("mbarrier.arrive.expect_tx.shared.b64 _, [%0], %1;" :: "r"(addr), "r"(tx) : "memory");
}
__device__ __forceinline__ void mbar_wait(uint32_t addr, uint32_t parity) {
    asm volatile(
        "{\n\t.reg .pred P;\n"
        "LW_%=:\n\t"
        "mbarrier.try_wait.parity.acquire.cluster.shared::cta.b64 P, [%0], %1, 0x989680;\n\t"
        "@P bra LD_%=;\n\t"
        "bra LW_%=;\n"
        "LD_%=:\n\t}"
        :: "r"(addr), "r"(parity) : "memory");
}
__device__ __forceinline__ void st_async_b64(uint32_t raddr, ull v, uint32_t rmbar) {
    asm volatile("st.async.shared::cluster.mbarrier::complete_tx::bytes.b64 [%0], %1, [%2];"
                 :: "r"(raddr), "l"(v), "r"(rmbar) : "memory");
}

// fast sigmoid / tanh (EX2 + RCP based; ~1e-6 rel err)
__device__ __forceinline__ float fsigm(float x) {
    return __fdividef(1.f, 1.f + __expf(-x));
}
__device__ __forceinline__ float ftanh_(float x) {
    return __fdividef(2.f, 1.f + __expf(-2.f * x)) - 1.f;
}

__device__ __forceinline__ void fma_bc(float4& a, float hs, const float4 w) {
    a.x = fmaf(hs, w.x, a.x);
    a.y = fmaf(hs, w.y, a.y);
    a.z = fmaf(hs, w.z, a.z);
    a.w = fmaf(hs, w.w, a.w);
}

// ---------------- tiled GEMM with bias: out[M,1024] = A[M,K] @ W[K,1024] + b ----------------
__global__ __launch_bounds__(256) void gemm_bias_kernel(
    const float* __restrict__ Aext,
    const float* __restrict__ W0, const float* __restrict__ W1,
    const float* __restrict__ b0, const float* __restrict__ b1,
    int M, int K, int mode)
{
    const int branch = blockIdx.z;
    const float* W = branch ? W1 : W0;
    const float* bias = branch ? b1 : b0;

    const float* A;
    float* out;
    if (mode == 0) {
        A = Aext;
        out = g_xz + (size_t)branch * (32u*1024u*1024u);
    } else if (mode == 1) {
        A = g_pool + (size_t)branch * (32*342*256);
        out = g_xz + (size_t)branch * (32u*342u*1024u);
    } else {
        A = g_hA + (size_t)branch * (32*342*256);
        out = g_xz + (size_t)branch * (32u*342u*1024u);
    }

    __shared__ float As[64][17];
    __shared__ float Bs[16][128];

    const int tid = threadIdx.x;
    const int tr = tid >> 5;
    const int tc = tid & 31;
    const int m0 = blockIdx.y * 64;
    const int n0 = blockIdx.x * 128;

    float acc[8][4];
    #pragma unroll
    for (int i = 0; i < 8; i++)
        #pragma unroll
        for (int j = 0; j < 4; j++) acc[i][j] = 0.f;

    for (int k0 = 0; k0 < K; k0 += 16) {
        #pragma unroll
        for (int i = tid; i < 1024; i += 256) {
            int m = i >> 4, k = i & 15;
            float v = 0.f;
            if (k0 + k < K) {
                v = A[(size_t)(m0 + m) * K + k0 + k];
                if (mode == 0) v = fminf(3.f, fmaxf(-3.f, v));
            }
            As[m][k] = v;
        }
        #pragma unroll
        for (int i = tid; i < 2048; i += 256) {
            int k = i >> 7, n = i & 127;
            Bs[k][n] = (k0 + k < K) ? W[(size_t)(k0 + k) * 1024 + n0 + n] : 0.f;
        }
        __syncthreads();
        #pragma unroll
        for (int k = 0; k < 16; k++) {
            float4 bv = *(const float4*)&Bs[k][tc * 4];
            #pragma unroll
            for (int i = 0; i < 8; i++) {
                float a = As[tr * 8 + i][k];
                acc[i][0] += a * bv.x;
                acc[i][1] += a * bv.y;
                acc[i][2] += a * bv.z;
                acc[i][3] += a * bv.w;
            }
        }
        __syncthreads();
    }
    float4 bv = *(const float4*)&bias[n0 + tc * 4];
    #pragma unroll
    for (int i = 0; i < 8; i++) {
        float4 r = make_float4(acc[i][0] + bv.x, acc[i][1] + bv.y,
                               acc[i][2] + bv.z, acc[i][3] + bv.w);
        *(float4*)&out[(size_t)(m0 + tr * 8 + i) * 1024 + n0 + tc * 4] = r;
    }
}

// ---------------- persistent recurrent LSTM kernel (8-CTA cluster gangs) ----------------
// grid = 128 blocks: blockIdx.x = gang*8 + cg; gang = branch*8 + bg; cg = cluster rank.
// Block owns 32 hidden units (j0 = cg*32), all 4 gates, all 256 k rows.
// 4-way batch pipeline: each step t runs 4 sub-steps (one batch each) with
// per-(batch,parity) mbarriers, so batch b's DSMEM h-exchange transits while
// batches b+1..b+3 compute. Gate role for batch b lives on warp b.
// Barriers at mbb + (par*4+b)*8, expect_tx = 8 CTAs * 32 units * 4B = 1024.
__global__ void __launch_bounds__(256, 1) __cluster_dims__(8, 1, 1)
lstm_rec_kernel(
    const float* __restrict__ Wr0, const float* __restrict__ Wr1,
    const int* __restrict__ x_len, int T, int mode)
{
    const int blk = blockIdx.x;
    const int gang = blk >> 3;
    const int cg = blk & 7;
    const int branch = gang >> 3;
    const int bg = gang & 7;
    const int j0 = cg * 32;
    const float* Wr = branch ? Wr1 : Wr0;

    const int tid = threadIdx.x;
    const int kg = tid >> 5;          // warp = k-group 0..7
    const int lane = tid & 31;
    const int kbase = kg * 32;

    __shared__ __align__(16) float h_s[2][4][256];    // double-buffered h (8KB)
    __shared__ __align__(16) float ps[8][4][128];     // partial sums (16KB)
    __shared__ __align__(8) ull mbar_s[8];

    // ---- mbarrier init + initial expects (idx = par*4 + b) ----
    const uint32_t mbb = smem_u32(&mbar_s[0]);
    if (tid == 0) {
        #pragma unroll
        for (int i = 0; i < 8; i++) mbar_init(mbb + i * 8, 1);
    }
    __syncthreads();
    if (tid == 0) {
        #pragma unroll
        for (int i = 0; i < 8; i++) mbar_expect(mbb + i * 8, 1024);
    }

    // ---- zero h(0) buffer ----
    {
        float* p = &h_s[0][0][0];
        #pragma unroll
        for (int i = tid; i < 1024; i += 256) p[i] = 0.f;
    }

    // ---- load weight slice into registers (once): 32 k x 4 cols ----
    float4 wreg[32];
    {
        const int c0 = lane * 4;
        const int gate = c0 >> 5;
        const int jj = c0 & 31;
        const float* wb = Wr + gate * 256 + j0 + jj;
        #pragma unroll
        for (int kk = 0; kk < 32; kk++) {
            const float* wr = wb + (size_t)(kbase + kk) * 1024;
            wreg[kk] = make_float4(wr[0], wr[1], wr[2], wr[3]);
        }
    }

    // ---- gate role: warp b handles batch b (warps 0-3), lane = unit gjj ----
    const int gb = tid >> 5;          // == warp id; valid as batch only if < 4
    const int gjj = tid & 31;
    const float NEGINF = __int_as_float(0xff800000);
    float cst = 0.f;
    float poolm = NEGINF;
    int mylen = 0;
    const int Tstride = (mode == 0) ? 1024 : 342;
    const float* xzg = nullptr;
    float *poolp = nullptr, *hop = nullptr;
    if (gb < 4) {
        const int b_glob = bg * 4 + gb;
        int xl = x_len[b_glob];
        mylen = (mode == 0) ? xl : (xl + 2) / 3;
        xzg = g_xz + (size_t)branch * 32u * (size_t)Tstride * 1024u
            + (size_t)b_glob * Tstride * 1024u + j0 + gjj;
        poolp = g_pool + ((size_t)(branch * 32 + b_glob) * 342) * 256 + j0 + gjj;
        hop = ((mode == 1) ? g_hA : g_hB) + ((size_t)(branch * 32 + b_glob) * 342) * 256 + j0 + gjj;
    }

    // peer base addresses (8 ranks)
    uint32_t peer_h[8], peer_mb[8];
    {
        const uint32_t hb = smem_u32(&h_s[0][0][0]);
        #pragma unroll
        for (int r = 0; r < 8; r++) {
            peer_h[r] = mapa_rank(hb, r);
            peer_mb[r] = mapa_rank(mbb, r);
        }
    }

    __syncthreads();
    // cluster sync: mbarriers + expects visible before any peer st.async
    asm volatile("barrier.cluster.arrive.aligned;" ::: "memory");
    asm volatile("barrier.cluster.wait.aligned;" ::: "memory");

    uint32_t phmask = 0;   // bit (par*4+b) = wait parity for that barrier

    for (int t = 0; t < T; t++) {
        const int par = t & 1;
        const int par1 = par ^ 1;

        // prefetch xz for this step (gate warps load their own batch's 4 gates)
        float x0, x1, x2, x3;
        if (gb < 4) {
            const float* p = xzg + (size_t)t * 1024;
            x0 = p[0]; x1 = p[256]; x2 = p[512]; x3 = p[768];
        }

        #pragma unroll
        for (int b = 0; b < 4; b++) {
            // ---- wait for h(b, t), re-arm for h(b, t+2) ----
            if (t > 0) {
                const uint32_t idx = (uint32_t)(par * 4 + b);
                mbar_wait(mbb + idx * 8u, (phmask >> idx) & 1u);
                phmask ^= 1u << idx;
                if (tid == 0) mbar_expect(mbb + idx * 8u, 1024);
            }

            // ---- GEMM batch b: own 32 k rows x 4 cols ----
            {
                float4 acc = make_float4(0.f, 0.f, 0.f, 0.f);
                #pragma unroll
                for (int kk4 = 0; kk4 < 8; kk4++) {
                    float4 h4 = *(const float4*)&h_s[par][b][kbase + 4 * kk4];
                    fma_bc(acc, h4.x, wreg[4 * kk4 + 0]);
                    fma_bc(acc, h4.y, wreg[4 * kk4 + 1]);
                    fma_bc(acc, h4.z, wreg[4 * kk4 + 2]);
                    fma_bc(acc, h4.w, wreg[4 * kk4 + 3]);
                }
                *(float4*)&ps[kg][b][4 * lane] = acc;
            }
            __syncthreads();

            // ---- gates batch b on warp b: reduce + math + send + store ----
            if (gb == b) {
                float zi = x0, zf = x1, zg = x2, zo = x3;
                #pragma unroll
                for (int q = 0; q < 8; q++) {
                    const float* pp = &ps[q][b][0];
                    zi += pp[gjj];
                    zf += pp[32 + gjj];
                    zg += pp[64 + gjj];
                    zo += pp[96 + gjj];
                }
                float iv = fsigm(zi), fv = fsigm(zf), gv = ftanh_(zg), ov = fsigm(zo);
                float cn = fv * cst + iv * gv;
                float hn = ov * ftanh_(cn);
                bool m = (t < mylen);
                float hp = h_s[par][b][j0 + gjj];
                float hv = m ? hn : hp;
                cst = m ? cn : cst;

                // pair-pack and send h(b, t+1) to all 8 cluster CTAs
                float hv_hi = __shfl_down_sync(0xffffffffu, hv, 1);
                if (t + 1 < T && (gjj & 1) == 0) {
                    ull hd;
                    asm("mov.b64 %0, {%1, %2};" : "=l"(hd) : "f"(hv), "f"(hv_hi));
                    const uint32_t off = (uint32_t)(((par1 * 4 + b) << 8) + j0 + gjj) * 4u;
                    const uint32_t moff = (uint32_t)(par1 * 4 + b) * 8u;
                    #pragma unroll
                    for (int r = 0; r < 8; r++)
                        st_async_b64(peer_h[r] + off, hd, peer_mb[r] + moff);
                }

                // outputs (off the signal path)
                if (mode == 0) {
                    poolm = fmaxf(poolm, hv);
                    if ((t % 3) == 1) {
                        poolp[(size_t)(t / 3) * 256] = poolm;
                        poolm = NEGINF;
                    }
                } else {
                    hop[(size_t)t * 256] = hv;
                }
            }
        }
    }

    // flush final pool window (covers t = 1022,1023)
    if (mode == 0 && gb < 4) {
        poolp[341u * 256] = poolm;
    }
}

// ---------------- CTC projection: out = hB @ ctc_w + ctc_b ----------------
__global__ __launch_bounds__(256) void ctc_kernel(
    const float* __restrict__ W, const float* __restrict__ bias, float* __restrict__ out)
{
    __shared__ float As[8][256];
    const int r0 = blockIdx.x * 8;
    for (int i = threadIdx.x; i < 2048; i += 256) {
        As[i >> 8][i & 255] = g_hB[(size_t)r0 * 256 + i];
    }
    __syncthreads();
    if (threadIdx.x < 240) {
        const int rl = threadIdx.x / 30;
        const int n = threadIdx.x % 30;
        float acc = bias[n];
        #pragma unroll 8
        for (int k = 0; k < 256; k++) acc += As[rl][k] * __ldg(&W[k * 30 + n]);
        const int r = r0 + rl;
        const int branch = r / 10944;
        const int idx = r - branch * 10944;
        const size_t o = (branch ? (size_t)OFF_CTC_C : (size_t)OFF_CTC_S) + (size_t)idx * 30 + n;
        out[o] = acc;
    }
}

// ---------------- lens + close ----------------
__global__ void finalize_kernel(const int* __restrict__ x_len, float* __restrict__ out)
{
    const int b = blockIdx.x;
    const float* s = out + OFF_CTC_S + (size_t)b * 10260;
    const float* c = out + OFF_CTC_C + (size_t)b * 10260;
    int ok = 1;
    for (int i = threadIdx.x; i < 10260; i += 256) {
        if (!(fabsf(s[i] - c[i]) < 1e-5f)) ok = 0;
    }
    int allok = __syncthreads_and(ok);
    if (threadIdx.x == 0) {
        float len = (float)((x_len[b] + 2) / 3);
        out[OFF_LEN_S + b] = len;
        out[OFF_LEN_C + b] = len;
        out[OFF_CLOSE + b] = allok ? 1.f : 0.f;
    }
}

// ---------------- launch ----------------
extern "C" void kernel_launch(void* const* d_in, const int* in_sizes, int n_in,
                              void* d_out, int out_size)
{
    const float* x      = (const float*)d_in[0];
    const int*   x_len  = (const int*)  d_in[1];
    const float* ws0_k  = (const float*)d_in[2];
    const float* ws0_r  = (const float*)d_in[3];
    const float* ws0_b  = (const float*)d_in[4];
    const float* ws1_k  = (const float*)d_in[5];
    const float* ws1_r  = (const float*)d_in[6];
    const float* ws1_b  = (const float*)d_in[7];
    const float* wc0_k  = (const float*)d_in[8];
    const float* wc0_r  = (const float*)d_in[9];
    const float* wc0_b  = (const float*)d_in[10];
    const float* wc1_k  = (const float*)d_in[11];
    const float* wc1_r  = (const float*)d_in[12];
    const float* wc1_b  = (const float*)d_in[13];
    const float* ctc_w  = (const float*)d_in[14];
    const float* ctc_b  = (const float*)d_in[15];
    float* out = (float*)d_out;

    // xz0 = clip(x) @ Wk0 + b0   (M = 32*1024, K = 40)
    gemm_bias_kernel<<<dim3(8, 512, 2), 256>>>(x, ws0_k, wc0_k, ws0_b, wc0_b, 32768, 40, 0);

    // lstm0 + fused maxpool3
    lstm_rec_kernel<<<128, 256>>>(ws0_r, wc0_r, x_len, 1024, 0);

    // xz1A = pooled @ Wk1 + b1   (M = 32*342, K = 256)
    gemm_bias_kernel<<<dim3(8, 171, 2), 256>>>(nullptr, ws1_k, wc1_k, ws1_b, wc1_b, 10944, 256, 1);

    // lstm1 pass A
    lstm_rec_kernel<<<128, 256>>>(ws1_r, wc1_r, x_len, 342, 1);

    // xz1B = hA @ Wk1 + b1
    gemm_bias_kernel<<<dim3(8, 171, 2), 256>>>(nullptr, ws1_k, wc1_k, ws1_b, wc1_b, 10944, 256, 2);

    // lstm1 pass B
    lstm_rec_kernel<<<128, 256>>>(ws1_r, wc1_r, x_len, 342, 2);

    // CTC projection for both branches
    ctc_kernel<<<2736, 256>>>(ctc_w, ctc_b, out);

    // lens + close
    finalize_kernel<<<32, 256>>>(x_len, out);
}

// round 11
// speedup vs baseline: 1.4089x; 1.4089x over previous
#include <cuda_runtime.h>
#include <math.h>
#include <stdint.h>

typedef unsigned long long ull;

// output layout (float32)
#define OFF_CTC_S 0
#define OFF_LEN_S 328320
#define OFF_CTC_C 328352
#define OFF_LEN_C 656672
#define OFF_CLOSE 656704

// ---------------- scratch (device globals; no allocation) ----------------
__device__ float g_xz[2u*32u*1024u*1024u];      // xz for lstm0; reused (smaller) for lstm1
__device__ float g_pool[2*32*342*256];          // pooled lstm0 output
__device__ float g_hA[2*32*342*256];            // lstm1 pass A output
__device__ float g_hB[2*32*342*256];            // lstm1 pass B output

// ---------------- cluster / mbarrier helpers ----------------
__device__ __forceinline__ uint32_t smem_u32(const void* p) {
    uint32_t a;
    asm("{ .reg .u64 t; cvta.to.shared.u64 t, %1; cvt.u32.u64 %0, t; }" : "=r"(a) : "l"(p));
    return a;
}
__device__ __forceinline__ uint32_t mapa_rank(uint32_t addr, uint32_t rank) {
    uint32_t r;
    asm("mapa.shared::cluster.u32 %0, %1, %2;" : "=r"(r) : "r"(addr), "r"(rank));
    return r;
}
__device__ __forceinline__ void mbar_init(uint32_t addr, uint32_t count) {
    asm volatile("mbarrier.init.shared.b64 [%0], %1;" :: "r"(addr), "r"(count) : "memory");
}
__device__ __forceinline__ void mbar_expect(uint32_t addr, uint32_t tx) {
    asm volatile("mbarrier.arrive.expect_tx.shared.b64 _, [%0], %1;" :: "r"(addr), "r"(tx) : "memory");
}
__device__ __forceinline__ void mbar_wait(uint32_t addr, uint32_t parity) {
    asm volatile(
        "{\n\t.reg .pred P;\n"
        "LW_%=:\n\t"
        "mbarrier.try_wait.parity.acquire.cluster.shared::cta.b64 P, [%0], %1, 0x989680;\n\t"
        "@P bra LD_%=;\n\t"
        "bra LW_%=;\n"
        "LD_%=:\n\t}"
        :: "r"(addr), "r"(parity) : "memory");
}
__device__ __forceinline__ void st_async_b64(uint32_t raddr, ull v, uint32_t rmbar) {
    asm volatile("st.async.shared::cluster.mbarrier::complete_tx::bytes.b64 [%0], %1, [%2];"
                 :: "r"(raddr), "l"(v), "r"(rmbar) : "memory");
}

// fast sigmoid / tanh (EX2 + RCP based; ~1e-6 rel err)
__device__ __forceinline__ float fsigm(float x) {
    return __fdividef(1.f, 1.f + __expf(-x));
}
__device__ __forceinline__ float ftanh_(float x) {
    return __fdividef(2.f, 1.f + __expf(-2.f * x)) - 1.f;
}

__device__ __forceinline__ void fma_bc(float4& a, float hs, const float4 w) {
    a.x = fmaf(hs, w.x, a.x);
    a.y = fmaf(hs, w.y, a.y);
    a.z = fmaf(hs, w.z, a.z);
    a.w = fmaf(hs, w.w, a.w);
}

// ---------------- tiled GEMM with bias (mode 0: xz0 = clip(x) @ Wk0 + b) ----------------
__global__ __launch_bounds__(256) void gemm_bias_kernel(
    const float* __restrict__ Aext,
    const float* __restrict__ W0, const float* __restrict__ W1,
    const float* __restrict__ b0, const float* __restrict__ b1,
    int M, int K)
{
    const int branch = blockIdx.z;
    const float* W = branch ? W1 : W0;
    const float* bias = branch ? b1 : b0;
    const float* A = Aext;
    float* out = g_xz + (size_t)branch * (32u*1024u*1024u);

    __shared__ float As[64][17];
    __shared__ float Bs[16][128];

    const int tid = threadIdx.x;
    const int tr = tid >> 5;
    const int tc = tid & 31;
    const int m0 = blockIdx.y * 64;
    const int n0 = blockIdx.x * 128;

    float acc[8][4];
    #pragma unroll
    for (int i = 0; i < 8; i++)
        #pragma unroll
        for (int j = 0; j < 4; j++) acc[i][j] = 0.f;

    for (int k0 = 0; k0 < K; k0 += 16) {
        #pragma unroll
        for (int i = tid; i < 1024; i += 256) {
            int m = i >> 4, k = i & 15;
            float v = 0.f;
            if (k0 + k < K) {
                v = A[(size_t)(m0 + m) * K + k0 + k];
                v = fminf(3.f, fmaxf(-3.f, v));
            }
            As[m][k] = v;
        }
        #pragma unroll
        for (int i = tid; i < 2048; i += 256) {
            int k = i >> 7, n = i & 127;
            Bs[k][n] = (k0 + k < K) ? W[(size_t)(k0 + k) * 1024 + n0 + n] : 0.f;
        }
        __syncthreads();
        #pragma unroll
        for (int k = 0; k < 16; k++) {
            float4 bv = *(const float4*)&Bs[k][tc * 4];
            #pragma unroll
            for (int i = 0; i < 8; i++) {
                float a = As[tr * 8 + i][k];
                acc[i][0] += a * bv.x;
                acc[i][1] += a * bv.y;
                acc[i][2] += a * bv.z;
                acc[i][3] += a * bv.w;
            }
        }
        __syncthreads();
    }
    float4 bv = *(const float4*)&bias[n0 + tc * 4];
    #pragma unroll
    for (int i = 0; i < 8; i++) {
        float4 r = make_float4(acc[i][0] + bv.x, acc[i][1] + bv.y,
                               acc[i][2] + bv.z, acc[i][3] + bv.w);
        *(float4*)&out[(size_t)(m0 + tr * 8 + i) * 1024 + n0 + tc * 4] = r;
    }
}

// ---------------- 128x128 tiled GEMM with bias (modes 1/2: lstm1 inputs) ----------------
// out[10944,1024] = A[10944,256] @ W[256,1024] + b.  8x8 microtile per thread.
__global__ __launch_bounds__(256) void gemm_bias128_kernel(
    const float* __restrict__ W0, const float* __restrict__ W1,
    const float* __restrict__ b0, const float* __restrict__ b1,
    int mode)
{
    const int branch = blockIdx.z;
    const float* W = branch ? W1 : W0;
    const float* bias = branch ? b1 : b0;
    const float* A = ((mode == 1) ? g_pool : g_hA) + (size_t)branch * (32*342*256);
    float* out = g_xz + (size_t)branch * (32u*342u*1024u);

    __shared__ float As[128][24];   // [m][k], padded (96B rows, 16B-aligned)
    __shared__ float Bs[16][132];   // [k][n], padded

    const int tid = threadIdx.x;
    const int ty = tid >> 4;        // 0..15 -> rows ty*8..+7
    const int tx = tid & 15;        // 0..15 -> cols tx*4..+3 and 64+tx*4..+3
    const int m0 = blockIdx.y * 128;
    const int n0 = blockIdx.x * 128;

    float acc[8][8];
    #pragma unroll
    for (int i = 0; i < 8; i++)
        #pragma unroll
        for (int j = 0; j < 8; j++) acc[i][j] = 0.f;

    for (int k0 = 0; k0 < 256; k0 += 16) {
        // A tile: 128 m x 16 k (2 float4 per thread)
        #pragma unroll
        for (int s = tid; s < 512; s += 256) {
            int m = s >> 2, kq = s & 3;
            float4 v = make_float4(0.f, 0.f, 0.f, 0.f);
            if (m0 + m < 10944)
                v = *(const float4*)&A[(size_t)(m0 + m) * 256 + k0 + kq * 4];
            *(float4*)&As[m][kq * 4] = v;
        }
        // B tile: 16 k x 128 n (2 float4 per thread)
        #pragma unroll
        for (int s = tid; s < 512; s += 256) {
            int k = s >> 5, nq = s & 31;
            *(float4*)&Bs[k][nq * 4] = *(const float4*)&W[(size_t)(k0 + k) * 1024 + n0 + nq * 4];
        }
        __syncthreads();
        #pragma unroll
        for (int k = 0; k < 16; k++) {
            float4 bb0 = *(const float4*)&Bs[k][tx * 4];
            float4 bb1 = *(const float4*)&Bs[k][64 + tx * 4];
            #pragma unroll
            for (int i = 0; i < 8; i++) {
                float a = As[ty * 8 + i][k];
                acc[i][0] = fmaf(a, bb0.x, acc[i][0]);
                acc[i][1] = fmaf(a, bb0.y, acc[i][1]);
                acc[i][2] = fmaf(a, bb0.z, acc[i][2]);
                acc[i][3] = fmaf(a, bb0.w, acc[i][3]);
                acc[i][4] = fmaf(a, bb1.x, acc[i][4]);
                acc[i][5] = fmaf(a, bb1.y, acc[i][5]);
                acc[i][6] = fmaf(a, bb1.z, acc[i][6]);
                acc[i][7] = fmaf(a, bb1.w, acc[i][7]);
            }
        }
        __syncthreads();
    }
    float4 bv0 = *(const float4*)&bias[n0 + tx * 4];
    float4 bv1 = *(const float4*)&bias[n0 + 64 + tx * 4];
    #pragma unroll
    for (int i = 0; i < 8; i++) {
        int m = m0 + ty * 8 + i;
        if (m < 10944) {
            float4 r0 = make_float4(acc[i][0] + bv0.x, acc[i][1] + bv0.y,
                                    acc[i][2] + bv0.z, acc[i][3] + bv0.w);
            float4 r1 = make_float4(acc[i][4] + bv1.x, acc[i][5] + bv1.y,
                                    acc[i][6] + bv1.z, acc[i][7] + bv1.w);
            *(float4*)&out[(size_t)m * 1024 + n0 + tx * 4] = r0;
            *(float4*)&out[(size_t)m * 1024 + n0 + 64 + tx * 4] = r1;
        }
    }
}

// ---------------- persistent recurrent LSTM kernel (8-CTA cluster gangs) ----------------
// grid = 128 blocks: blockIdx.x = gang*8 + cg; gang = branch*8 + bg; cg = cluster rank.
// Block owns 32 hidden units (j0 = cg*32), all 4 gates, all 256 k rows.
// The gang's 4 batches form TWO independent 2-batch chains (A = batches 0-1,
// B = batches 2-3, same Wr -> shared register weights). Chains alternate inside
// the step so each chain's DSMEM transit hides under the other chain's compute.
// Barriers at mbb + (par*2 + chain)*8; expect_tx = 8 CTAs * 2b * 32 units * 4B = 2048.
__global__ void __launch_bounds__(256, 1) __cluster_dims__(8, 1, 1)
lstm_rec_kernel(
    const float* __restrict__ Wr0, const float* __restrict__ Wr1,
    const int* __restrict__ x_len, int T, int mode)
{
    const int blk = blockIdx.x;
    const int gang = blk >> 3;
    const int cg = blk & 7;
    const int branch = gang >> 3;
    const int bg = gang & 7;
    const int j0 = cg * 32;
    const float* Wr = branch ? Wr1 : Wr0;

    const int tid = threadIdx.x;
    const int kg = tid >> 5;          // warp = k-group 0..7
    const int lane = tid & 31;
    const int kbase = kg * 32;

    __shared__ __align__(16) float h_s[2][4][256];    // double-buffered h (8KB)
    __shared__ __align__(16) float ps[8][4][128];     // partial sums (16KB)
    __shared__ __align__(8) ull mbar_s[4];

    // ---- mbarrier init + initial expects (idx = par*2 + chain) ----
    const uint32_t mbb = smem_u32(&mbar_s[0]);
    if (tid == 0) {
        #pragma unroll
        for (int i = 0; i < 4; i++) mbar_init(mbb + i * 8, 1);
    }
    __syncthreads();
    if (tid == 0) {
        #pragma unroll
        for (int i = 0; i < 4; i++) mbar_expect(mbb + i * 8, 2048);
    }

    // ---- zero h(0) buffer ----
    {
        float* p = &h_s[0][0][0];
        #pragma unroll
        for (int i = tid; i < 1024; i += 256) p[i] = 0.f;
    }

    // ---- load weight slice into registers (once): 32 k x 4 cols ----
    float4 wreg[32];
    {
        const int c0 = lane * 4;
        const int gate = c0 >> 5;
        const int jj = c0 & 31;
        const float* wb = Wr + gate * 256 + j0 + jj;
        #pragma unroll
        for (int kk = 0; kk < 32; kk++) {
            const float* wr = wb + (size_t)(kbase + kk) * 1024;
            wreg[kk] = make_float4(wr[0], wr[1], wr[2], wr[3]);
        }
    }

    // ---- gate role (tid < 128): gb = tid>>5 (batch-in-group), gjj = tid&31 ----
    const int gb = tid >> 5;
    const int gjj = tid & 31;
    const float NEGINF = __int_as_float(0xff800000);
    float cst = 0.f;
    float poolm = NEGINF;
    int mylen = 0;
    const int Tstride = (mode == 0) ? 1024 : 342;
    const float* xzg = nullptr;
    float *poolp = nullptr, *hop = nullptr;
    if (tid < 128) {
        const int b_glob = bg * 4 + gb;
        int xl = x_len[b_glob];
        mylen = (mode == 0) ? xl : (xl + 2) / 3;
        xzg = g_xz + (size_t)branch * 32u * (size_t)Tstride * 1024u
            + (size_t)b_glob * Tstride * 1024u + j0 + gjj;
        poolp = g_pool + ((size_t)(branch * 32 + b_glob) * 342) * 256 + j0 + gjj;
        hop = ((mode == 1) ? g_hA : g_hB) + ((size_t)(branch * 32 + b_glob) * 342) * 256 + j0 + gjj;
    }

    // peer base addresses (8 ranks)
    uint32_t peer_h[8], peer_mb[8];
    {
        const uint32_t hb = smem_u32(&h_s[0][0][0]);
        #pragma unroll
        for (int r = 0; r < 8; r++) {
            peer_h[r] = mapa_rank(hb, r);
            peer_mb[r] = mapa_rank(mbb, r);
        }
    }

    __syncthreads();
    // cluster sync: mbarriers + expects visible before any peer st.async
    asm volatile("barrier.cluster.arrive.aligned;" ::: "memory");
    asm volatile("barrier.cluster.wait.aligned;" ::: "memory");

    uint32_t phmask = 0;   // bit (par*2 + chain) = wait parity for that barrier

    for (int t = 0; t < T; t++) {
        const int par = t & 1;
        const int par1 = par ^ 1;

        // prefetch xz for this step (gate warps load their own batch's 4 gates)
        float x0, x1, x2, x3;
        if (tid < 128) {
            const float* p = xzg + (size_t)t * 1024;
            x0 = p[0]; x1 = p[256]; x2 = p[512]; x3 = p[768];
        }

        // ================= chain A (batches 0,1) =================
        if (t > 0) {
            const uint32_t idx = (uint32_t)(par * 2);
            mbar_wait(mbb + idx * 8u, (phmask >> idx) & 1u);
            phmask ^= 1u << idx;
            if (tid == 0) mbar_expect(mbb + idx * 8u, 2048);
        }
        #pragma unroll
        for (int b = 0; b < 2; b++) {
            float4 acc = make_float4(0.f, 0.f, 0.f, 0.f);
            #pragma unroll
            for (int kk4 = 0; kk4 < 8; kk4++) {
                float4 h4 = *(const float4*)&h_s[par][b][kbase + 4 * kk4];
                fma_bc(acc, h4.x, wreg[4 * kk4 + 0]);
                fma_bc(acc, h4.y, wreg[4 * kk4 + 1]);
                fma_bc(acc, h4.z, wreg[4 * kk4 + 2]);
                fma_bc(acc, h4.w, wreg[4 * kk4 + 3]);
            }
            *(float4*)&ps[kg][b][4 * lane] = acc;
        }
        __syncthreads();
        if (tid < 64) {   // gates for batches 0,1 (warps 0-1)
            float zi = x0, zf = x1, zg = x2, zo = x3;
            #pragma unroll
            for (int q = 0; q < 8; q++) {
                const float* pp = &ps[q][gb][0];
                zi += pp[gjj];
                zf += pp[32 + gjj];
                zg += pp[64 + gjj];
                zo += pp[96 + gjj];
            }
            float iv = fsigm(zi), fv = fsigm(zf), gv = ftanh_(zg), ov = fsigm(zo);
            float cn = fv * cst + iv * gv;
            float hn = ov * ftanh_(cn);
            bool m = (t < mylen);
            float hp = h_s[par][gb][j0 + gjj];
            float hv = m ? hn : hp;
            cst = m ? cn : cst;

            float hv_hi = __shfl_down_sync(0xffffffffu, hv, 1);
            if (t + 1 < T && (gjj & 1) == 0) {
                ull hd;
                asm("mov.b64 %0, {%1, %2};" : "=l"(hd) : "f"(hv), "f"(hv_hi));
                const uint32_t off = (uint32_t)(((par1 * 4 + gb) << 8) + j0 + gjj) * 4u;
                const uint32_t moff = (uint32_t)(par1 * 2) * 8u;
                #pragma unroll
                for (int r = 0; r < 8; r++)
                    st_async_b64(peer_h[r] + off, hd, peer_mb[r] + moff);
            }

            if (mode == 0) {
                poolm = fmaxf(poolm, hv);
                if ((t % 3) == 1) {
                    poolp[(size_t)(t / 3) * 256] = poolm;
                    poolm = NEGINF;
                }
            } else {
                hop[(size_t)t * 256] = hv;
            }
        }

        // ================= chain B (batches 2,3) =================
        if (t > 0) {
            const uint32_t idx = (uint32_t)(par * 2 + 1);
            mbar_wait(mbb + idx * 8u, (phmask >> idx) & 1u);
            phmask ^= 1u << idx;
            if (tid == 0) mbar_expect(mbb + idx * 8u, 2048);
        }
        #pragma unroll
        for (int b = 2; b < 4; b++) {
            float4 acc = make_float4(0.f, 0.f, 0.f, 0.f);
            #pragma unroll
            for (int kk4 = 0; kk4 < 8; kk4++) {
                float4 h4 = *(const float4*)&h_s[par][b][kbase + 4 * kk4];
                fma_bc(acc, h4.x, wreg[4 * kk4 + 0]);
                fma_bc(acc, h4.y, wreg[4 * kk4 + 1]);
                fma_bc(acc, h4.z, wreg[4 * kk4 + 2]);
                fma_bc(acc, h4.w, wreg[4 * kk4 + 3]);
            }
            *(float4*)&ps[kg][b][4 * lane] = acc;
        }
        __syncthreads();
        if (tid >= 64 && tid < 128) {   // gates for batches 2,3 (warps 2-3)
            float zi = x0, zf = x1, zg = x2, zo = x3;
            #pragma unroll
            for (int q = 0; q < 8; q++) {
                const float* pp = &ps[q][gb][0];
                zi += pp[gjj];
                zf += pp[32 + gjj];
                zg += pp[64 + gjj];
                zo += pp[96 + gjj];
            }
            float iv = fsigm(zi), fv = fsigm(zf), gv = ftanh_(zg), ov = fsigm(zo);
            float cn = fv * cst + iv * gv;
            float hn = ov * ftanh_(cn);
            bool m = (t < mylen);
            float hp = h_s[par][gb][j0 + gjj];
            float hv = m ? hn : hp;
            cst = m ? cn : cst;

            float hv_hi = __shfl_down_sync(0xffffffffu, hv, 1);
            if (t + 1 < T && (gjj & 1) == 0) {
                ull hd;
                asm("mov.b64 %0, {%1, %2};" : "=l"(hd) : "f"(hv), "f"(hv_hi));
                const uint32_t off = (uint32_t)(((par1 * 4 + gb) << 8) + j0 + gjj) * 4u;
                const uint32_t moff = (uint32_t)(par1 * 2 + 1) * 8u;
                #pragma unroll
                for (int r = 0; r < 8; r++)
                    st_async_b64(peer_h[r] + off, hd, peer_mb[r] + moff);
            }

            if (mode == 0) {
                poolm = fmaxf(poolm, hv);
                if ((t % 3) == 1) {
                    poolp[(size_t)(t / 3) * 256] = poolm;
                    poolm = NEGINF;
                }
            } else {
                hop[(size_t)t * 256] = hv;
            }
        }
    }

    // flush final pool window (covers t = 1022,1023)
    if (mode == 0 && tid < 128) {
        poolp[341u * 256] = poolm;
    }
}

// ---------------- CTC projection: out = hB @ ctc_w + ctc_b ----------------
__global__ __launch_bounds__(256) void ctc_kernel(
    const float* __restrict__ W, const float* __restrict__ bias, float* __restrict__ out)
{
    __shared__ float As[8][256];
    const int r0 = blockIdx.x * 8;
    for (int i = threadIdx.x; i < 2048; i += 256) {
        As[i >> 8][i & 255] = g_hB[(size_t)r0 * 256 + i];
    }
    __syncthreads();
    if (threadIdx.x < 240) {
        const int rl = threadIdx.x / 30;
        const int n = threadIdx.x % 30;
        float acc = bias[n];
        #pragma unroll 8
        for (int k = 0; k < 256; k++) acc += As[rl][k] * __ldg(&W[k * 30 + n]);
        const int r = r0 + rl;
        const int branch = r / 10944;
        const int idx = r - branch * 10944;
        const size_t o = (branch ? (size_t)OFF_CTC_C : (size_t)OFF_CTC_S) + (size_t)idx * 30 + n;
        out[o] = acc;
    }
}

// ---------------- lens + close ----------------
__global__ void finalize_kernel(const int* __restrict__ x_len, float* __restrict__ out)
{
    const int b = blockIdx.x;
    const float* s = out + OFF_CTC_S + (size_t)b * 10260;
    const float* c = out + OFF_CTC_C + (size_t)b * 10260;
    int ok = 1;
    for (int i = threadIdx.x; i < 10260; i += 256) {
        if (!(fabsf(s[i] - c[i]) < 1e-5f)) ok = 0;
    }
    int allok = __syncthreads_and(ok);
    if (threadIdx.x == 0) {
        float len = (float)((x_len[b] + 2) / 3);
        out[OFF_LEN_S + b] = len;
        out[OFF_LEN_C + b] = len;
        out[OFF_CLOSE + b] = allok ? 1.f : 0.f;
    }
}

// ---------------- launch ----------------
extern "C" void kernel_launch(void* const* d_in, const int* in_sizes, int n_in,
                              void* d_out, int out_size)
{
    const float* x      = (const float*)d_in[0];
    const int*   x_len  = (const int*)  d_in[1];
    const float* ws0_k  = (const float*)d_in[2];
    const float* ws0_r  = (const float*)d_in[3];
    const float* ws0_b  = (const float*)d_in[4];
    const float* ws1_k  = (const float*)d_in[5];
    const float* ws1_r  = (const float*)d_in[6];
    const float* ws1_b  = (const float*)d_in[7];
    const float* wc0_k  = (const float*)d_in[8];
    const float* wc0_r  = (const float*)d_in[9];
    const float* wc0_b  = (const float*)d_in[10];
    const float* wc1_k  = (const float*)d_in[11];
    const float* wc1_r  = (const float*)d_in[12];
    const float* wc1_b  = (const float*)d_in[13];
    const float* ctc_w  = (const float*)d_in[14];
    const float* ctc_b  = (const float*)d_in[15];
    float* out = (float*)d_out;

    // xz0 = clip(x) @ Wk0 + b0   (M = 32*1024, K = 40)
    gemm_bias_kernel<<<dim3(8, 512, 2), 256>>>(x, ws0_k, wc0_k, ws0_b, wc0_b, 32768, 40);

    // lstm0 + fused maxpool3
    lstm_rec_kernel<<<128, 256>>>(ws0_r, wc0_r, x_len, 1024, 0);

    // xz1A = pooled @ Wk1 + b1   (M = 32*342, K = 256)
    gemm_bias128_kernel<<<dim3(8, 86, 2), 256>>>(ws1_k, wc1_k, ws1_b, wc1_b, 1);

    // lstm1 pass A
    lstm_rec_kernel<<<128, 256>>>(ws1_r, wc1_r, x_len, 342, 1);

    // xz1B = hA @ Wk1 + b1
    gemm_bias128_kernel<<<dim3(8, 86, 2), 256>>>(ws1_k, wc1_k, ws1_b, wc1_b, 2);

    // lstm1 pass B
    lstm_rec_kernel<<<128, 256>>>(ws1_r, wc1_r, x_len, 342, 2);

    // CTC projection for both branches
    ctc_kernel<<<2736, 256>>>(ctc_w, ctc_b, out);

    // lens + close
    finalize_kernel<<<32, 256>>>(x_len, out);
}

// round 12
// speedup vs baseline: 1.4834x; 1.0529x over previous
#include <cuda_runtime.h>
#include <math.h>
#include <stdint.h>

typedef unsigned long long ull;

// output layout (float32)
#define OFF_CTC_S 0
#define OFF_LEN_S 328320
#define OFF_CTC_C 328352
#define OFF_LEN_C 656672
#define OFF_CLOSE 656704

// ---------------- scratch (device globals; no allocation) ----------------
__device__ float g_pool[2*32*342*256];          // pooled lstm0 output
__device__ float g_hA[2*32*342*256];            // lstm1 pass A output
__device__ float g_hB[2*32*342*256];            // lstm1 pass B output

// ---------------- cluster / mbarrier helpers ----------------
__device__ __forceinline__ uint32_t smem_u32(const void* p) {
    uint32_t a;
    asm("{ .reg .u64 t; cvta.to.shared.u64 t, %1; cvt.u32.u64 %0, t; }" : "=r"(a) : "l"(p));
    return a;
}
__device__ __forceinline__ uint32_t mapa_rank(uint32_t addr, uint32_t rank) {
    uint32_t r;
    asm("mapa.shared::cluster.u32 %0, %1, %2;" : "=r"(r) : "r"(addr), "r"(rank));
    return r;
}
__device__ __forceinline__ void mbar_init(uint32_t addr, uint32_t count) {
    asm volatile("mbarrier.init.shared.b64 [%0], %1;" :: "r"(addr), "r"(count) : "memory");
}
__device__ __forceinline__ void mbar_expect(uint32_t addr, uint32_t tx) {
    asm volatile("mbarrier.arrive.expect_tx.shared.b64 _, [%0], %1;" :: "r"(addr), "r"(tx) : "memory");
}
__device__ __forceinline__ void mbar_wait(uint32_t addr, uint32_t parity) {
    asm volatile(
        "{\n\t.reg .pred P;\n"
        "LW_%=:\n\t"
        "mbarrier.try_wait.parity.acquire.cluster.shared::cta.b64 P, [%0], %1, 0x989680;\n\t"
        "@P bra LD_%=;\n\t"
        "bra LW_%=;\n"
        "LD_%=:\n\t}"
        :: "r"(addr), "r"(parity) : "memory");
}
__device__ __forceinline__ void st_async_b64(uint32_t raddr, ull v, uint32_t rmbar) {
    asm volatile("st.async.shared::cluster.mbarrier::complete_tx::bytes.b64 [%0], %1, [%2];"
                 :: "r"(raddr), "l"(v), "r"(rmbar) : "memory");
}

// fast sigmoid / tanh (EX2 + RCP based; ~1e-6 rel err)
__device__ __forceinline__ float fsigm(float x) {
    return __fdividef(1.f, 1.f + __expf(-x));
}
__device__ __forceinline__ float ftanh_(float x) {
    return __fdividef(2.f, 1.f + __expf(-2.f * x)) - 1.f;
}

__device__ __forceinline__ void fma_bc(float4& a, float hs, const float4 w) {
    a.x = fmaf(hs, w.x, a.x);
    a.y = fmaf(hs, w.y, a.y);
    a.z = fmaf(hs, w.z, a.z);
    a.w = fmaf(hs, w.w, a.w);
}

// ======================================================================
// lstm0: fused  xz = clip(x)@Wk + b  +  recurrence  +  maxpool3(SAME)
// grid = 128: blockIdx.x = (branch*8 + bg)*8 + cg (cg = cluster rank).
// Warp kg owns h-rows kg*32..+31 AND x-rows kg*5..+4 (K=40); lane owns
// 4 local cols. xz partial accumulates into the SAME registers pre-wait.
// Exchange: b64 st.async, 2 batch-split mbarriers per parity (round-9).
// ======================================================================
__global__ void __launch_bounds__(256, 1) __cluster_dims__(8, 1, 1)
lstm0_kernel(
    const float* __restrict__ Wr0, const float* __restrict__ Wr1,
    const float* __restrict__ Wk0, const float* __restrict__ Wk1,
    const float* __restrict__ bias0, const float* __restrict__ bias1,
    const float* __restrict__ x, const int* __restrict__ x_len)
{
    const int T = 1024;
    const int blk = blockIdx.x;
    const int gang = blk >> 3;
    const int cg = blk & 7;
    const int branch = gang >> 3;
    const int bg = gang & 7;
    const int j0 = cg * 32;
    const float* Wr = branch ? Wr1 : Wr0;
    const float* Wk = branch ? Wk1 : Wk0;
    const float* bias = branch ? bias1 : bias0;

    const int tid = threadIdx.x;
    const int kg = tid >> 5;
    const int lane = tid & 31;
    const int kbase = kg * 32;

    __shared__ __align__(16) float h_s[2][4][256];     // 8KB
    __shared__ __align__(16) float ps[8][4][128];      // 16KB
    __shared__ __align__(16) float4 wk0s[40 * 32];     // 20KB  [k][lane]
    __shared__ __align__(16) float inp_s[2][4][40];    // 1.28KB
    __shared__ __align__(8) ull mbar_s[4];

    const uint32_t mbb = smem_u32(&mbar_s[0]);
    if (tid == 0) {
        #pragma unroll
        for (int i = 0; i < 4; i++) mbar_init(mbb + i * 8, 1);
    }
    __syncthreads();
    if (tid == 0) {
        #pragma unroll
        for (int i = 0; i < 4; i++) mbar_expect(mbb + i * 8, 2048);
    }

    // zero h(0)
    {
        float* p = &h_s[0][0][0];
        #pragma unroll
        for (int i = tid; i < 1024; i += 256) p[i] = 0.f;
    }

    // Wr slice -> registers
    float4 wreg[32];
    {
        const int c0 = lane * 4;
        const int gate = c0 >> 5;
        const int jj = c0 & 31;
        const float* wb = Wr + gate * 256 + j0 + jj;
        #pragma unroll
        for (int kk = 0; kk < 32; kk++) {
            const float* wr = wb + (size_t)(kbase + kk) * 1024;
            wreg[kk] = make_float4(wr[0], wr[1], wr[2], wr[3]);
        }
    }
    // Wk slice -> SMEM  [40][32 float4]
    for (int i = tid; i < 40 * 32; i += 256) {
        const int k = i >> 5, l = i & 31;
        const int c0 = l * 4;
        const int gate = c0 >> 5, jj = c0 & 31;
        const float* p = Wk + (size_t)k * 1024 + gate * 256 + j0 + jj;
        wk0s[i] = make_float4(p[0], p[1], p[2], p[3]);
    }

    // gate role (tid < 128)
    const int gb = tid >> 5;
    const int gjj = tid & 31;
    const float NEGINF = __int_as_float(0xff800000);
    float cst = 0.f, poolm = NEGINF;
    int mylen = 0;
    float bi = 0.f, bf_ = 0.f, bg2 = 0.f, bo = 0.f;
    float *poolp = nullptr;
    if (tid < 128) {
        const int b_glob = bg * 4 + gb;
        mylen = x_len[b_glob];
        poolp = g_pool + ((size_t)(branch * 32 + b_glob) * 342) * 256 + j0 + gjj;
        bi  = bias[          j0 + gjj];
        bf_ = bias[256  + j0 + gjj];
        bg2 = bias[512  + j0 + gjj];
        bo  = bias[768  + j0 + gjj];
    }

    // preload inp(0)
    if (tid < 160) {
        const int b = tid / 40, f = tid % 40;
        float v = x[((size_t)(bg * 4 + b) * 1024 + 0) * 40 + f];
        inp_s[0][b][f] = fminf(3.f, fmaxf(-3.f, v));
    }

    // peer addresses
    uint32_t peer_h[8], peer_mb[8];
    {
        const uint32_t hb = smem_u32(&h_s[0][0][0]);
        #pragma unroll
        for (int r = 0; r < 8; r++) {
            peer_h[r] = mapa_rank(hb, r);
            peer_mb[r] = mapa_rank(mbb, r);
        }
    }

    __syncthreads();
    asm volatile("barrier.cluster.arrive.aligned;" ::: "memory");
    asm volatile("barrier.cluster.wait.aligned;" ::: "memory");

    uint32_t phmask = 0;

    for (int t = 0; t < T; t++) {
        const int par = t & 1;
        const int par1 = par ^ 1;

        // A) prefetch x(t+1) (regs; independent)
        float xnext = 0.f;
        if (tid < 160) {
            const int b = tid / 40, f = tid % 40;
            const int tt = (t + 1 < T) ? t + 1 : t;
            xnext = x[((size_t)(bg * 4 + b) * 1024 + tt) * 40 + f];
            xnext = fminf(3.f, fmaxf(-3.f, xnext));
        }

        // B) xz partial into acc (pre-wait): warp kg covers x-rows kg*5..+4
        float4 acc[4];
        #pragma unroll
        for (int b = 0; b < 4; b++) acc[b] = make_float4(0.f, 0.f, 0.f, 0.f);
        #pragma unroll
        for (int kk = 0; kk < 5; kk++) {
            const int k = kg * 5 + kk;
            const float4 w = wk0s[k * 32 + lane];
            fma_bc(acc[0], inp_s[par][0][k], w);
            fma_bc(acc[1], inp_s[par][1][k], w);
            fma_bc(acc[2], inp_s[par][2][k], w);
            fma_bc(acc[3], inp_s[par][3][k], w);
        }

        // C) wait for h(t) on both batch-split barriers, re-arm
        if (t > 0) {
            const uint32_t base = mbb + (par ? 16u : 0u);
            const uint32_t ph = (phmask >> par) & 1u;
            mbar_wait(base, ph);
            mbar_wait(base + 8, ph);
            phmask ^= 1u << par;
            if (tid == 0) { mbar_expect(base, 2048); mbar_expect(base + 8, 2048); }
        }

        // D) h-GEMM continues on acc
        #pragma unroll
        for (int b = 0; b < 4; b++) {
            #pragma unroll
            for (int kk4 = 0; kk4 < 8; kk4++) {
                float4 h4 = *(const float4*)&h_s[par][b][kbase + 4 * kk4];
                fma_bc(acc[b], h4.x, wreg[4 * kk4 + 0]);
                fma_bc(acc[b], h4.y, wreg[4 * kk4 + 1]);
                fma_bc(acc[b], h4.z, wreg[4 * kk4 + 2]);
                fma_bc(acc[b], h4.w, wreg[4 * kk4 + 3]);
            }
            *(float4*)&ps[kg][b][4 * lane] = acc[b];
        }
        // E) stage inp(t+1)
        if (tid < 160) inp_s[par1][tid / 40][tid % 40] = xnext;
        __syncthreads();

        // F) gates: reduce + math + send + pool
        if (tid < 128) {
            float zi = bi, zf = bf_, zg = bg2, zo = bo;
            #pragma unroll
            for (int q = 0; q < 8; q++) {
                const float* pp = &ps[q][gb][0];
                zi += pp[gjj];
                zf += pp[32 + gjj];
                zg += pp[64 + gjj];
                zo += pp[96 + gjj];
            }
            float iv = fsigm(zi), fv = fsigm(zf), gv = ftanh_(zg), ov = fsigm(zo);
            float cn = fv * cst + iv * gv;
            float hn = ov * ftanh_(cn);
            bool m = (t < mylen);
            float hp = h_s[par][gb][j0 + gjj];
            float hv = m ? hn : hp;
            cst = m ? cn : cst;

            float hv_hi = __shfl_down_sync(0xffffffffu, hv, 1);
            if (t + 1 < T && (gjj & 1) == 0) {
                ull hd;
                asm("mov.b64 %0, {%1, %2};" : "=l"(hd) : "f"(hv), "f"(hv_hi));
                const uint32_t off = (uint32_t)(((par1 * 4 + gb) << 8) + j0 + gjj) * 4u;
                const uint32_t moff = (par1 ? 16u : 0u) + ((uint32_t)(gb >> 1) << 3);
                #pragma unroll
                for (int r = 0; r < 8; r++)
                    st_async_b64(peer_h[r] + off, hd, peer_mb[r] + moff);
            }

            poolm = fmaxf(poolm, hv);
            if ((t % 3) == 1) {
                poolp[(size_t)(t / 3) * 256] = poolm;
                poolm = NEGINF;
            }
        }
    }
    if (tid < 128) poolp[341u * 256] = poolm;   // final window (t=1022,1023)
}

// ======================================================================
// lstm1: fused  xz = inp@Wk1 + b  (K=256, Wk1 slice in dynamic SMEM)
// + recurrence.  inp = g_pool (mode 1) or g_hA (mode 2); out g_hA / g_hB.
// ======================================================================
#define SM1_WK    0           // float4[256*32] = 131072 B
#define SM1_H     131072      // float[2][4][256] = 8192 B
#define SM1_PS    139264      // float[8][4][128] = 16384 B
#define SM1_INP   155648      // float[2][4][256] = 8192 B
#define SM1_MBAR  163840      // 4 mbarriers
#define SM1_TOTAL 163904

extern __shared__ __align__(16) char smdyn[];

__global__ void __launch_bounds__(256, 1) __cluster_dims__(8, 1, 1)
lstm1_kernel(
    const float* __restrict__ Wr0, const float* __restrict__ Wr1,
    const float* __restrict__ Wk0, const float* __restrict__ Wk1,
    const float* __restrict__ bias0, const float* __restrict__ bias1,
    const int* __restrict__ x_len, int mode)
{
    const int T = 342;
    float4* wk1s = (float4*)(smdyn + SM1_WK);
    float (*h_s)[4][256] = (float (*)[4][256])(smdyn + SM1_H);
    float (*ps)[4][128]  = (float (*)[4][128])(smdyn + SM1_PS);
    float (*inp_s)[4][256] = (float (*)[4][256])(smdyn + SM1_INP);

    const int blk = blockIdx.x;
    const int gang = blk >> 3;
    const int cg = blk & 7;
    const int branch = gang >> 3;
    const int bg = gang & 7;
    const int j0 = cg * 32;
    const float* Wr = branch ? Wr1 : Wr0;
    const float* Wk = branch ? Wk1 : Wk0;
    const float* bias = branch ? bias1 : bias0;

    const int tid = threadIdx.x;
    const int kg = tid >> 5;
    const int lane = tid & 31;
    const int kbase = kg * 32;

    const uint32_t mbb = smem_u32(smdyn + SM1_MBAR);
    if (tid == 0) {
        #pragma unroll
        for (int i = 0; i < 4; i++) mbar_init(mbb + i * 8, 1);
    }
    __syncthreads();
    if (tid == 0) {
        #pragma unroll
        for (int i = 0; i < 4; i++) mbar_expect(mbb + i * 8, 2048);
    }

    // zero h(0)
    {
        float* p = &h_s[0][0][0];
        #pragma unroll
        for (int i = tid; i < 1024; i += 256) p[i] = 0.f;
    }

    // Wr slice -> registers
    float4 wreg[32];
    {
        const int c0 = lane * 4;
        const int gate = c0 >> 5;
        const int jj = c0 & 31;
        const float* wb = Wr + gate * 256 + j0 + jj;
        #pragma unroll
        for (int kk = 0; kk < 32; kk++) {
            const float* wr = wb + (size_t)(kbase + kk) * 1024;
            wreg[kk] = make_float4(wr[0], wr[1], wr[2], wr[3]);
        }
    }
    // Wk1 slice -> SMEM  [256][32 float4]
    for (int i = tid; i < 256 * 32; i += 256) {
        const int k = i >> 5, l = i & 31;
        const int c0 = l * 4;
        const int gate = c0 >> 5, jj = c0 & 31;
        const float* p = Wk + (size_t)k * 1024 + gate * 256 + j0 + jj;
        wk1s[i] = make_float4(p[0], p[1], p[2], p[3]);
    }

    // gate role
    const int gb = tid >> 5;
    const int gjj = tid & 31;
    float cst = 0.f;
    int mylen = 0;
    float bi = 0.f, bf_ = 0.f, bg2 = 0.f, bo = 0.f;
    float* hop = nullptr;
    if (tid < 128) {
        const int b_glob = bg * 4 + gb;
        mylen = (x_len[b_glob] + 2) / 3;
        hop = ((mode == 1) ? g_hA : g_hB) + ((size_t)(branch * 32 + b_glob) * 342) * 256 + j0 + gjj;
        bi  = bias[          j0 + gjj];
        bf_ = bias[256  + j0 + gjj];
        bg2 = bias[512  + j0 + gjj];
        bo  = bias[768  + j0 + gjj];
    }

    // inp source + preload inp(0): tid -> b = tid>>6, k4 = tid&63 (float4)
    const float* src = ((mode == 1) ? g_pool : g_hA)
                     + (size_t)(branch * 32 + bg * 4) * 342 * 256;
    {
        const int b = tid >> 6, k4 = tid & 63;
        float4 v = *(const float4*)&src[((size_t)b * 342 + 0) * 256 + k4 * 4];
        *(float4*)&inp_s[0][b][k4 * 4] = v;
    }

    // peer addresses
    uint32_t peer_h[8], peer_mb[8];
    {
        const uint32_t hb = smem_u32(&h_s[0][0][0]);
        #pragma unroll
        for (int r = 0; r < 8; r++) {
            peer_h[r] = mapa_rank(hb, r);
            peer_mb[r] = mapa_rank(mbb, r);
        }
    }

    __syncthreads();
    asm volatile("barrier.cluster.arrive.aligned;" ::: "memory");
    asm volatile("barrier.cluster.wait.aligned;" ::: "memory");

    uint32_t phmask = 0;

    for (int t = 0; t < T; t++) {
        const int par = t & 1;
        const int par1 = par ^ 1;

        // A) prefetch inp(t+1) (regs)
        float4 xnext;
        {
            const int b = tid >> 6, k4 = tid & 63;
            const int tt = (t + 1 < T) ? t + 1 : t;
            xnext = *(const float4*)&src[((size_t)b * 342 + tt) * 256 + k4 * 4];
        }

        // B) xz partial into acc (pre-wait): warp kg covers inp-rows kbase..+31
        float4 acc[4];
        #pragma unroll
        for (int b = 0; b < 4; b++) acc[b] = make_float4(0.f, 0.f, 0.f, 0.f);
        #pragma unroll
        for (int kk4 = 0; kk4 < 8; kk4++) {
            const int k = kbase + 4 * kk4;
            const float4 w0 = wk1s[(k + 0) * 32 + lane];
            const float4 w1 = wk1s[(k + 1) * 32 + lane];
            const float4 w2 = wk1s[(k + 2) * 32 + lane];
            const float4 w3 = wk1s[(k + 3) * 32 + lane];
            #pragma unroll
            for (int b = 0; b < 4; b++) {
                float4 p = *(const float4*)&inp_s[par][b][k];
                fma_bc(acc[b], p.x, w0);
                fma_bc(acc[b], p.y, w1);
                fma_bc(acc[b], p.z, w2);
                fma_bc(acc[b], p.w, w3);
            }
        }

        // C) wait for h(t), re-arm
        if (t > 0) {
            const uint32_t base = mbb + (par ? 16u : 0u);
            const uint32_t ph = (phmask >> par) & 1u;
            mbar_wait(base, ph);
            mbar_wait(base + 8, ph);
            phmask ^= 1u << par;
            if (tid == 0) { mbar_expect(base, 2048); mbar_expect(base + 8, 2048); }
        }

        // D) h-GEMM continues on acc
        #pragma unroll
        for (int b = 0; b < 4; b++) {
            #pragma unroll
            for (int kk4 = 0; kk4 < 8; kk4++) {
                float4 h4 = *(const float4*)&h_s[par][b][kbase + 4 * kk4];
                fma_bc(acc[b], h4.x, wreg[4 * kk4 + 0]);
                fma_bc(acc[b], h4.y, wreg[4 * kk4 + 1]);
                fma_bc(acc[b], h4.z, wreg[4 * kk4 + 2]);
                fma_bc(acc[b], h4.w, wreg[4 * kk4 + 3]);
            }
            *(float4*)&ps[kg][b][4 * lane] = acc[b];
        }
        // E) stage inp(t+1)
        {
            const int b = tid >> 6, k4 = tid & 63;
            *(float4*)&inp_s[par1][b][k4 * 4] = xnext;
        }
        __syncthreads();

        // F) gates
        if (tid < 128) {
            float zi = bi, zf = bf_, zg = bg2, zo = bo;
            #pragma unroll
            for (int q = 0; q < 8; q++) {
                const float* pp = &ps[q][gb][0];
                zi += pp[gjj];
                zf += pp[32 + gjj];
                zg += pp[64 + gjj];
                zo += pp[96 + gjj];
            }
            float iv = fsigm(zi), fv = fsigm(zf), gv = ftanh_(zg), ov = fsigm(zo);
            float cn = fv * cst + iv * gv;
            float hn = ov * ftanh_(cn);
            bool m = (t < mylen);
            float hp = h_s[par][gb][j0 + gjj];
            float hv = m ? hn : hp;
            cst = m ? cn : cst;

            float hv_hi = __shfl_down_sync(0xffffffffu, hv, 1);
            if (t + 1 < T && (gjj & 1) == 0) {
                ull hd;
                asm("mov.b64 %0, {%1, %2};" : "=l"(hd) : "f"(hv), "f"(hv_hi));
                const uint32_t off = (uint32_t)(((par1 * 4 + gb) << 8) + j0 + gjj) * 4u;
                const uint32_t moff = (par1 ? 16u : 0u) + ((uint32_t)(gb >> 1) << 3);
                #pragma unroll
                for (int r = 0; r < 8; r++)
                    st_async_b64(peer_h[r] + off, hd, peer_mb[r] + moff);
            }

            hop[(size_t)t * 256] = hv;
        }
    }
}

// ---------------- CTC projection: out = hB @ ctc_w + ctc_b ----------------
__global__ __launch_bounds__(256) void ctc_kernel(
    const float* __restrict__ W, const float* __restrict__ bias, float* __restrict__ out)
{
    __shared__ float As[8][256];
    const int r0 = blockIdx.x * 8;
    for (int i = threadIdx.x; i < 2048; i += 256) {
        As[i >> 8][i & 255] = g_hB[(size_t)r0 * 256 + i];
    }
    __syncthreads();
    if (threadIdx.x < 240) {
        const int rl = threadIdx.x / 30;
        const int n = threadIdx.x % 30;
        float acc = bias[n];
        #pragma unroll 8
        for (int k = 0; k < 256; k++) acc += As[rl][k] * __ldg(&W[k * 30 + n]);
        const int r = r0 + rl;
        const int branch = r / 10944;
        const int idx = r - branch * 10944;
        const size_t o = (branch ? (size_t)OFF_CTC_C : (size_t)OFF_CTC_S) + (size_t)idx * 30 + n;
        out[o] = acc;
    }
}

// ---------------- lens + close ----------------
__global__ void finalize_kernel(const int* __restrict__ x_len, float* __restrict__ out)
{
    const int b = blockIdx.x;
    const float* s = out + OFF_CTC_S + (size_t)b * 10260;
    const float* c = out + OFF_CTC_C + (size_t)b * 10260;
    int ok = 1;
    for (int i = threadIdx.x; i < 10260; i += 256) {
        if (!(fabsf(s[i] - c[i]) < 1e-5f)) ok = 0;
    }
    int allok = __syncthreads_and(ok);
    if (threadIdx.x == 0) {
        float len = (float)((x_len[b] + 2) / 3);
        out[OFF_LEN_S + b] = len;
        out[OFF_LEN_C + b] = len;
        out[OFF_CLOSE + b] = allok ? 1.f : 0.f;
    }
}

// ---------------- launch ----------------
extern "C" void kernel_launch(void* const* d_in, const int* in_sizes, int n_in,
                              void* d_out, int out_size)
{
    const float* x      = (const float*)d_in[0];
    const int*   x_len  = (const int*)  d_in[1];
    const float* ws0_k  = (const float*)d_in[2];
    const float* ws0_r  = (const float*)d_in[3];
    const float* ws0_b  = (const float*)d_in[4];
    const float* ws1_k  = (const float*)d_in[5];
    const float* ws1_r  = (const float*)d_in[6];
    const float* ws1_b  = (const float*)d_in[7];
    const float* wc0_k  = (const float*)d_in[8];
    const float* wc0_r  = (const float*)d_in[9];
    const float* wc0_b  = (const float*)d_in[10];
    const float* wc1_k  = (const float*)d_in[11];
    const float* wc1_r  = (const float*)d_in[12];
    const float* wc1_b  = (const float*)d_in[13];
    const float* ctc_w  = (const float*)d_in[14];
    const float* ctc_b  = (const float*)d_in[15];
    float* out = (float*)d_out;

    static int smem_set = 0;
    if (!smem_set) {
        cudaFuncSetAttribute(lstm1_kernel,
                             cudaFuncAttributeMaxDynamicSharedMemorySize, SM1_TOTAL);
        smem_set = 1;
    }

    // lstm0 with fused clip+xz+maxpool3 (both branches, 128 CTAs)
    lstm0_kernel<<<128, 256>>>(ws0_r, wc0_r, ws0_k, wc0_k, ws0_b, wc0_b, x, x_len);

    // lstm1 pass A (fused xz from g_pool)
    lstm1_kernel<<<128, 256, SM1_TOTAL>>>(ws1_r, wc1_r, ws1_k, wc1_k, ws1_b, wc1_b, x_len, 1);

    // lstm1 pass B (fused xz from g_hA)
    lstm1_kernel<<<128, 256, SM1_TOTAL>>>(ws1_r, wc1_r, ws1_k, wc1_k, ws1_b, wc1_b, x_len, 2);

    // CTC projection for both branches
    ctc_kernel<<<2736, 256>>>(ctc_w, ctc_b, out);

    // lens + close
    finalize_kernel<<<32, 256>>>(x_len, out);
}

// round 13
// speedup vs baseline: 1.6372x; 1.1037x over previous
#include <cuda_runtime.h>
#include <math.h>
#include <stdint.h>

typedef unsigned long long ull;

// output layout (float32)
#define OFF_CTC_S 0
#define OFF_LEN_S 328320
#define OFF_CTC_C 328352
#define OFF_LEN_C 656672
#define OFF_CLOSE 656704

// ---------------- scratch (device globals; no allocation) ----------------
__device__ float g_xz[2u*32u*1024u*1024u];      // xz for lstm0; reused (smaller) for lstm1
__device__ float g_pool[2*32*342*256];          // pooled lstm0 output
__device__ float g_hA[2*32*342*256];            // lstm1 pass A output
__device__ float g_hB[2*32*342*256];            // lstm1 pass B output

// ---------------- cluster / mbarrier helpers ----------------
__device__ __forceinline__ uint32_t smem_u32(const void* p) {
    uint32_t a;
    asm("{ .reg .u64 t; cvta.to.shared.u64 t, %1; cvt.u32.u64 %0, t; }" : "=r"(a) : "l"(p));
    return a;
}
__device__ __forceinline__ uint32_t mapa_rank(uint32_t addr, uint32_t rank) {
    uint32_t r;
    asm("mapa.shared::cluster.u32 %0, %1, %2;" : "=r"(r) : "r"(addr), "r"(rank));
    return r;
}
__device__ __forceinline__ void mbar_init(uint32_t addr, uint32_t count) {
    asm volatile("mbarrier.init.shared.b64 [%0], %1;" :: "r"(addr), "r"(count) : "memory");
}
__device__ __forceinline__ void mbar_expect(uint32_t addr, uint32_t tx) {
    asm volatile("mbarrier.arrive.expect_tx.shared.b64 _, [%0], %1;" :: "r"(addr), "r"(tx) : "memory");
}
__device__ __forceinline__ void mbar_wait(uint32_t addr, uint32_t parity) {
    asm volatile(
        "{\n\t.reg .pred P;\n"
        "LW_%=:\n\t"
        "mbarrier.try_wait.parity.acquire.cluster.shared::cta.b64 P, [%0], %1, 0x989680;\n\t"
        "@P bra LD_%=;\n\t"
        "bra LW_%=;\n"
        "LD_%=:\n\t}"
        :: "r"(addr), "r"(parity) : "memory");
}
__device__ __forceinline__ void st_async_b64(uint32_t raddr, ull v, uint32_t rmbar) {
    asm volatile("st.async.shared::cluster.mbarrier::complete_tx::bytes.b64 [%0], %1, [%2];"
                 :: "r"(raddr), "l"(v), "r"(rmbar) : "memory");
}

// fast sigmoid / tanh (EX2 + RCP based; ~1e-6 rel err)
__device__ __forceinline__ float fsigm(float x) {
    return __fdividef(1.f, 1.f + __expf(-x));
}
__device__ __forceinline__ float ftanh_(float x) {
    return __fdividef(2.f, 1.f + __expf(-2.f * x)) - 1.f;
}

__device__ __forceinline__ void fma_bc(float4& a, float hs, const float4 w) {
    a.x = fmaf(hs, w.x, a.x);
    a.y = fmaf(hs, w.y, a.y);
    a.z = fmaf(hs, w.z, a.z);
    a.w = fmaf(hs, w.w, a.w);
}

// ---------------- tiled GEMM with bias (mode 0: xz0 = clip(x) @ Wk0 + b) ----------------
__global__ __launch_bounds__(256) void gemm_bias_kernel(
    const float* __restrict__ Aext,
    const float* __restrict__ W0, const float* __restrict__ W1,
    const float* __restrict__ b0, const float* __restrict__ b1,
    int M, int K)
{
    const int branch = blockIdx.z;
    const float* W = branch ? W1 : W0;
    const float* bias = branch ? b1 : b0;
    const float* A = Aext;
    float* out = g_xz + (size_t)branch * (32u*1024u*1024u);

    __shared__ float As[64][17];
    __shared__ float Bs[16][128];

    const int tid = threadIdx.x;
    const int tr = tid >> 5;
    const int tc = tid & 31;
    const int m0 = blockIdx.y * 64;
    const int n0 = blockIdx.x * 128;

    float acc[8][4];
    #pragma unroll
    for (int i = 0; i < 8; i++)
        #pragma unroll
        for (int j = 0; j < 4; j++) acc[i][j] = 0.f;

    for (int k0 = 0; k0 < K; k0 += 16) {
        #pragma unroll
        for (int i = tid; i < 1024; i += 256) {
            int m = i >> 4, k = i & 15;
            float v = 0.f;
            if (k0 + k < K) {
                v = A[(size_t)(m0 + m) * K + k0 + k];
                v = fminf(3.f, fmaxf(-3.f, v));
            }
            As[m][k] = v;
        }
        #pragma unroll
        for (int i = tid; i < 2048; i += 256) {
            int k = i >> 7, n = i & 127;
            Bs[k][n] = (k0 + k < K) ? W[(size_t)(k0 + k) * 1024 + n0 + n] : 0.f;
        }
        __syncthreads();
        #pragma unroll
        for (int k = 0; k < 16; k++) {
            float4 bv = *(const float4*)&Bs[k][tc * 4];
            #pragma unroll
            for (int i = 0; i < 8; i++) {
                float a = As[tr * 8 + i][k];
                acc[i][0] += a * bv.x;
                acc[i][1] += a * bv.y;
                acc[i][2] += a * bv.z;
                acc[i][3] += a * bv.w;
            }
        }
        __syncthreads();
    }
    float4 bv = *(const float4*)&bias[n0 + tc * 4];
    #pragma unroll
    for (int i = 0; i < 8; i++) {
        float4 r = make_float4(acc[i][0] + bv.x, acc[i][1] + bv.y,
                               acc[i][2] + bv.z, acc[i][3] + bv.w);
        *(float4*)&out[(size_t)(m0 + tr * 8 + i) * 1024 + n0 + tc * 4] = r;
    }
}

// ---------------- 128x128 tiled GEMM with bias (modes 1/2: lstm1 inputs) ----------------
// out[10944,1024] = A[10944,256] @ W[256,1024] + b.  8x8 microtile per thread.
__global__ __launch_bounds__(256) void gemm_bias128_kernel(
    const float* __restrict__ W0, const float* __restrict__ W1,
    const float* __restrict__ b0, const float* __restrict__ b1,
    int mode)
{
    const int branch = blockIdx.z;
    const float* W = branch ? W1 : W0;
    const float* bias = branch ? b1 : b0;
    const float* A = ((mode == 1) ? g_pool : g_hA) + (size_t)branch * (32*342*256);
    float* out = g_xz + (size_t)branch * (32u*342u*1024u);

    __shared__ float As[128][24];   // [m][k], padded
    __shared__ float Bs[16][132];   // [k][n], padded

    const int tid = threadIdx.x;
    const int ty = tid >> 4;        // 0..15 -> rows ty*8..+7
    const int tx = tid & 15;        // 0..15 -> cols tx*4..+3 and 64+tx*4..+3
    const int m0 = blockIdx.y * 128;
    const int n0 = blockIdx.x * 128;

    float acc[8][8];
    #pragma unroll
    for (int i = 0; i < 8; i++)
        #pragma unroll
        for (int j = 0; j < 8; j++) acc[i][j] = 0.f;

    for (int k0 = 0; k0 < 256; k0 += 16) {
        #pragma unroll
        for (int s = tid; s < 512; s += 256) {
            int m = s >> 2, kq = s & 3;
            float4 v = make_float4(0.f, 0.f, 0.f, 0.f);
            if (m0 + m < 10944)
                v = *(const float4*)&A[(size_t)(m0 + m) * 256 + k0 + kq * 4];
            *(float4*)&As[m][kq * 4] = v;
        }
        #pragma unroll
        for (int s = tid; s < 512; s += 256) {
            int k = s >> 5, nq = s & 31;
            *(float4*)&Bs[k][nq * 4] = *(const float4*)&W[(size_t)(k0 + k) * 1024 + n0 + nq * 4];
        }
        __syncthreads();
        #pragma unroll
        for (int k = 0; k < 16; k++) {
            float4 bb0 = *(const float4*)&Bs[k][tx * 4];
            float4 bb1 = *(const float4*)&Bs[k][64 + tx * 4];
            #pragma unroll
            for (int i = 0; i < 8; i++) {
                float a = As[ty * 8 + i][k];
                acc[i][0] = fmaf(a, bb0.x, acc[i][0]);
                acc[i][1] = fmaf(a, bb0.y, acc[i][1]);
                acc[i][2] = fmaf(a, bb0.z, acc[i][2]);
                acc[i][3] = fmaf(a, bb0.w, acc[i][3]);
                acc[i][4] = fmaf(a, bb1.x, acc[i][4]);
                acc[i][5] = fmaf(a, bb1.y, acc[i][5]);
                acc[i][6] = fmaf(a, bb1.z, acc[i][6]);
                acc[i][7] = fmaf(a, bb1.w, acc[i][7]);
            }
        }
        __syncthreads();
    }
    float4 bv0 = *(const float4*)&bias[n0 + tx * 4];
    float4 bv1 = *(const float4*)&bias[n0 + 64 + tx * 4];
    #pragma unroll
    for (int i = 0; i < 8; i++) {
        int m = m0 + ty * 8 + i;
        if (m < 10944) {
            float4 r0 = make_float4(acc[i][0] + bv0.x, acc[i][1] + bv0.y,
                                    acc[i][2] + bv0.z, acc[i][3] + bv0.w);
            float4 r1 = make_float4(acc[i][4] + bv1.x, acc[i][5] + bv1.y,
                                    acc[i][6] + bv1.z, acc[i][7] + bv1.w);
            *(float4*)&out[(size_t)m * 1024 + n0 + tx * 4] = r0;
            *(float4*)&out[(size_t)m * 1024 + n0 + 64 + tx * 4] = r1;
        }
    }
}

// ---------------- persistent recurrent LSTM kernel (8-CTA cluster gangs) ----------------
// EXACT round-9 kernel (best measured: 4650 cyc/step).
// grid = 128 blocks: blockIdx.x = gang*8 + cg; gang = branch*8 + bg; cg = cluster rank.
// Block owns 32 hidden units (j0 = cg*32), all 4 gates (128 local cols), all 256 k rows.
// h exchange: b64-packed st.async (even lanes, pair-shuffled) to all 8 CTAs,
// completing on 2 batch-split mbarriers per parity (expect_tx 2048B each).
__global__ void __launch_bounds__(256, 1) __cluster_dims__(8, 1, 1)
lstm_rec_kernel(
    const float* __restrict__ Wr0, const float* __restrict__ Wr1,
    const int* __restrict__ x_len, int T, int mode)
{
    const int blk = blockIdx.x;
    const int gang = blk >> 3;
    const int cg = blk & 7;
    const int branch = gang >> 3;
    const int bg = gang & 7;
    const int j0 = cg * 32;
    const float* Wr = branch ? Wr1 : Wr0;

    const int tid = threadIdx.x;
    const int kg = tid >> 5;          // warp = k-group 0..7
    const int lane = tid & 31;
    const int kbase = kg * 32;

    __shared__ __align__(16) float h_s[2][4][256];    // double-buffered h (8KB)
    __shared__ __align__(16) float ps[8][4][128];     // partial sums (16KB)
    __shared__ __align__(8) ull mbar_s[4];

    // ---- mbarrier init + initial expects ----
    const uint32_t mbb = smem_u32(&mbar_s[0]);
    if (tid == 0) {
        mbar_init(mbb + 0, 1);  mbar_init(mbb + 8, 1);
        mbar_init(mbb + 16, 1); mbar_init(mbb + 24, 1);
    }
    __syncthreads();
    if (tid == 0) {
        mbar_expect(mbb + 0, 2048);  mbar_expect(mbb + 8, 2048);   // parity0: h(2)
        mbar_expect(mbb + 16, 2048); mbar_expect(mbb + 24, 2048);  // parity1: h(1)
    }

    // ---- zero h(0) buffer ----
    {
        float* p = &h_s[0][0][0];
        #pragma unroll
        for (int i = tid; i < 1024; i += 256) p[i] = 0.f;
    }

    // ---- load weight slice into registers (once): 32 k x 4 cols ----
    float4 wreg[32];
    {
        const int c0 = lane * 4;
        const int gate = c0 >> 5;
        const int jj = c0 & 31;
        const float* wb = Wr + gate * 256 + j0 + jj;
        #pragma unroll
        for (int kk = 0; kk < 32; kk++) {
            const float* wr = wb + (size_t)(kbase + kk) * 1024;
            wreg[kk] = make_float4(wr[0], wr[1], wr[2], wr[3]);
        }
    }

    // ---- gate role (tid < 128): gb = tid>>5, gjj = tid&31 ----
    const int gb = tid >> 5;
    const int gjj = tid & 31;
    const float NEGINF = __int_as_float(0xff800000);
    float cst = 0.f;
    float poolm = NEGINF;
    int mylen = 0;
    const int Tstride = (mode == 0) ? 1024 : 342;
    const float* xzg = nullptr;
    float *poolp = nullptr, *hop = nullptr;
    if (tid < 128) {
        const int b_glob = bg * 4 + gb;
        int xl = x_len[b_glob];
        mylen = (mode == 0) ? xl : (xl + 2) / 3;
        xzg = g_xz + (size_t)branch * 32u * (size_t)Tstride * 1024u
            + (size_t)b_glob * Tstride * 1024u + j0 + gjj;
        poolp = g_pool + ((size_t)(branch * 32 + b_glob) * 342) * 256 + j0 + gjj;
        hop = ((mode == 1) ? g_hA : g_hB) + ((size_t)(branch * 32 + b_glob) * 342) * 256 + j0 + gjj;
    }

    // peer base addresses (8 ranks)
    uint32_t peer_h[8], peer_mb[8];
    {
        const uint32_t hb = smem_u32(&h_s[0][0][0]);
        #pragma unroll
        for (int r = 0; r < 8; r++) {
            peer_h[r] = mapa_rank(hb, r);
            peer_mb[r] = mapa_rank(mbb, r);
        }
    }

    __syncthreads();
    // cluster sync: mbarriers + expects visible before any peer st.async
    asm volatile("barrier.cluster.arrive.aligned;" ::: "memory");
    asm volatile("barrier.cluster.wait.aligned;" ::: "memory");

    uint32_t phase0 = 0, phase1 = 0;

    for (int t = 0; t < T; t++) {
        const int par = t & 1;
        const int par1 = par ^ 1;

        // prefetch xz for this step (gate threads; independent of h)
        float x0, x1, x2, x3;
        if (tid < 128) {
            const float* p = xzg + (size_t)t * 1024;
            x0 = p[0]; x1 = p[256]; x2 = p[512]; x3 = p[768];
        }

        // ---- wait for h(t) on both batch-split barriers, re-arm for h(t+2) ----
        if (t > 0) {
            const uint32_t base = mbb + (par ? 16u : 0u);
            if (par) { mbar_wait(base, phase1); mbar_wait(base + 8, phase1); phase1 ^= 1; }
            else     { mbar_wait(base, phase0); mbar_wait(base + 8, phase0); phase0 ^= 1; }
            if (tid == 0) { mbar_expect(base, 2048); mbar_expect(base + 8, 2048); }
        }

        // ---- GEMM: partial z over owned 32 k rows, 4 cols, 4 batches ----
        #pragma unroll
        for (int b = 0; b < 4; b++) {
            float4 acc = make_float4(0.f, 0.f, 0.f, 0.f);
            #pragma unroll
            for (int kk4 = 0; kk4 < 8; kk4++) {
                float4 h4 = *(const float4*)&h_s[par][b][kbase + 4 * kk4];
                fma_bc(acc, h4.x, wreg[4 * kk4 + 0]);
                fma_bc(acc, h4.y, wreg[4 * kk4 + 1]);
                fma_bc(acc, h4.z, wreg[4 * kk4 + 2]);
                fma_bc(acc, h4.w, wreg[4 * kk4 + 3]);
            }
            *(float4*)&ps[kg][b][4 * lane] = acc;
        }
        __syncthreads();

        // ---- gates: fused 8-way reduce + math + packed publish (gate warps) ----
        if (tid < 128) {
            float zi = x0, zf = x1, zg = x2, zo = x3;
            #pragma unroll
            for (int q = 0; q < 8; q++) {
                const float* pp = &ps[q][gb][0];
                zi += pp[gjj];
                zf += pp[32 + gjj];
                zg += pp[64 + gjj];
                zo += pp[96 + gjj];
            }
            float iv = fsigm(zi), fv = fsigm(zf), gv = ftanh_(zg), ov = fsigm(zo);
            float cn = fv * cst + iv * gv;
            float hn = ov * ftanh_(cn);
            bool m = (t < mylen);
            float hp = h_s[par][gb][j0 + gjj];
            float hv = m ? hn : hp;
            cst = m ? cn : cst;

            // pair-pack and send h(t+1) to all 8 cluster CTAs (even lanes, b64)
            float hv_hi = __shfl_down_sync(0xffffffffu, hv, 1);
            if (t + 1 < T && (gjj & 1) == 0) {
                ull hd;
                asm("mov.b64 %0, {%1, %2};" : "=l"(hd) : "f"(hv), "f"(hv_hi));
                const uint32_t off = (uint32_t)(((par1 * 4 + gb) << 8) + j0 + gjj) * 4u;
                const uint32_t moff = (par1 ? 16u : 0u) + ((uint32_t)(gb >> 1) << 3);
                #pragma unroll
                for (int r = 0; r < 8; r++)
                    st_async_b64(peer_h[r] + off, hd, peer_mb[r] + moff);
            }

            // outputs (after sends — off the signal path)
            if (mode == 0) {
                poolm = fmaxf(poolm, hv);
                if ((t % 3) == 1) {
                    poolp[(size_t)(t / 3) * 256] = poolm;
                    poolm = NEGINF;
                }
            } else {
                hop[(size_t)t * 256] = hv;
            }
        }
    }

    // flush final pool window (covers t = 1022,1023)
    if (mode == 0 && tid < 128) {
        poolp[341u * 256] = poolm;
    }
}

// ---------------- CTC projection: out = hB @ ctc_w + ctc_b ----------------
__global__ __launch_bounds__(256) void ctc_kernel(
    const float* __restrict__ W, const float* __restrict__ bias, float* __restrict__ out)
{
    __shared__ float As[8][256];
    const int r0 = blockIdx.x * 8;
    for (int i = threadIdx.x; i < 2048; i += 256) {
        As[i >> 8][i & 255] = g_hB[(size_t)r0 * 256 + i];
    }
    __syncthreads();
    if (threadIdx.x < 240) {
        const int rl = threadIdx.x / 30;
        const int n = threadIdx.x % 30;
        float acc = bias[n];
        #pragma unroll 8
        for (int k = 0; k < 256; k++) acc += As[rl][k] * __ldg(&W[k * 30 + n]);
        const int r = r0 + rl;
        const int branch = r / 10944;
        const int idx = r - branch * 10944;
        const size_t o = (branch ? (size_t)OFF_CTC_C : (size_t)OFF_CTC_S) + (size_t)idx * 30 + n;
        out[o] = acc;
    }
}

// ---------------- lens + close ----------------
__global__ void finalize_kernel(const int* __restrict__ x_len, float* __restrict__ out)
{
    const int b = blockIdx.x;
    const float* s = out + OFF_CTC_S + (size_t)b * 10260;
    const float* c = out + OFF_CTC_C + (size_t)b * 10260;
    int ok = 1;
    for (int i = threadIdx.x; i < 10260; i += 256) {
        if (!(fabsf(s[i] - c[i]) < 1e-5f)) ok = 0;
    }
    int allok = __syncthreads_and(ok);
    if (threadIdx.x == 0) {
        float len = (float)((x_len[b] + 2) / 3);
        out[OFF_LEN_S + b] = len;
        out[OFF_LEN_C + b] = len;
        out[OFF_CLOSE + b] = allok ? 1.f : 0.f;
    }
}

// ---------------- launch ----------------
extern "C" void kernel_launch(void* const* d_in, const int* in_sizes, int n_in,
                              void* d_out, int out_size)
{
    const float* x      = (const float*)d_in[0];
    const int*   x_len  = (const int*)  d_in[1];
    const float* ws0_k  = (const float*)d_in[2];
    const float* ws0_r  = (const float*)d_in[3];
    const float* ws0_b  = (const float*)d_in[4];
    const float* ws1_k  = (const float*)d_in[5];
    const float* ws1_r  = (const float*)d_in[6];
    const float* ws1_b  = (const float*)d_in[7];
    const float* wc0_k  = (const float*)d_in[8];
    const float* wc0_r  = (const float*)d_in[9];
    const float* wc0_b  = (const float*)d_in[10];
    const float* wc1_k  = (const float*)d_in[11];
    const float* wc1_r  = (const float*)d_in[12];
    const float* wc1_b  = (const float*)d_in[13];
    const float* ctc_w  = (const float*)d_in[14];
    const float* ctc_b  = (const float*)d_in[15];
    float* out = (float*)d_out;

    // xz0 = clip(x) @ Wk0 + b0   (M = 32*1024, K = 40)
    gemm_bias_kernel<<<dim3(8, 512, 2), 256>>>(x, ws0_k, wc0_k, ws0_b, wc0_b, 32768, 40);

    // lstm0 + fused maxpool3
    lstm_rec_kernel<<<128, 256>>>(ws0_r, wc0_r, x_len, 1024, 0);

    // xz1A = pooled @ Wk1 + b1   (M = 32*342, K = 256)
    gemm_bias128_kernel<<<dim3(8, 86, 2), 256>>>(ws1_k, wc1_k, ws1_b, wc1_b, 1);

    // lstm1 pass A
    lstm_rec_kernel<<<128, 256>>>(ws1_r, wc1_r, x_len, 342, 1);

    // xz1B = hA @ Wk1 + b1
    gemm_bias128_kernel<<<dim3(8, 86, 2), 256>>>(ws1_k, wc1_k, ws1_b, wc1_b, 2);

    // lstm1 pass B
    lstm_rec_kernel<<<128, 256>>>(ws1_r, wc1_r, x_len, 342, 2);

    // CTC projection for both branches
    ctc_kernel<<<2736, 256>>>(ctc_w, ctc_b, out);

    // lens + close
    finalize_kernel<<<32, 256>>>(x_len, out);
}

// round 14
// speedup vs baseline: 1.7081x; 1.0433x over previous
#include <cuda_runtime.h>
#include <math.h>
#include <stdint.h>

typedef unsigned long long ull;

// output layout (float32)
#define OFF_CTC_S 0
#define OFF_LEN_S 328320
#define OFF_CTC_C 328352
#define OFF_LEN_C 656672
#define OFF_CLOSE 656704

// ---------------- scratch (device globals; no allocation) ----------------
__device__ float g_xz[2u*32u*1024u*1024u];      // xz for lstm0; reused (smaller) for lstm1
__device__ float g_pool[2*32*342*256];          // pooled lstm0 output
__device__ float g_hA[2*32*342*256];            // lstm1 pass A output
__device__ float g_hB[2*32*342*256];            // lstm1 pass B output

// ---------------- cluster / mbarrier helpers ----------------
__device__ __forceinline__ uint32_t smem_u32(const void* p) {
    uint32_t a;
    asm("{ .reg .u64 t; cvta.to.shared.u64 t, %1; cvt.u32.u64 %0, t; }" : "=r"(a) : "l"(p));
    return a;
}
__device__ __forceinline__ uint32_t mapa_rank(uint32_t addr, uint32_t rank) {
    uint32_t r;
    asm("mapa.shared::cluster.u32 %0, %1, %2;" : "=r"(r) : "r"(addr), "r"(rank));
    return r;
}
__device__ __forceinline__ void mbar_init(uint32_t addr, uint32_t count) {
    asm volatile("mbarrier.init.shared.b64 [%0], %1;" :: "r"(addr), "r"(count) : "memory");
}
__device__ __forceinline__ void mbar_expect(uint32_t addr, uint32_t tx) {
    asm volatile("mbarrier.arrive.expect_tx.shared.b64 _, [%0], %1;" :: "r"(addr), "r"(tx) : "memory");
}
__device__ __forceinline__ void mbar_wait(uint32_t addr, uint32_t parity) {
    asm volatile(
        "{\n\t.reg .pred P;\n"
        "LW_%=:\n\t"
        "mbarrier.try_wait.parity.acquire.cluster.shared::cta.b64 P, [%0], %1, 0x989680;\n\t"
        "@P bra LD_%=;\n\t"
        "bra LW_%=;\n"
        "LD_%=:\n\t}"
        :: "r"(addr), "r"(parity) : "memory");
}
__device__ __forceinline__ void st_async_b64(uint32_t raddr, ull v, uint32_t rmbar) {
    asm volatile("st.async.shared::cluster.mbarrier::complete_tx::bytes.b64 [%0], %1, [%2];"
                 :: "r"(raddr), "l"(v), "r"(rmbar) : "memory");
}

// fast sigmoid / tanh (EX2 + RCP based; ~1e-6 rel err)
__device__ __forceinline__ float fsigm(float x) {
    return __fdividef(1.f, 1.f + __expf(-x));
}
__device__ __forceinline__ float ftanh_(float x) {
    return __fdividef(2.f, 1.f + __expf(-2.f * x)) - 1.f;
}

__device__ __forceinline__ void fma_bc(float4& a, float hs, const float4 w) {
    a.x = fmaf(hs, w.x, a.x);
    a.y = fmaf(hs, w.y, a.y);
    a.z = fmaf(hs, w.z, a.z);
    a.w = fmaf(hs, w.w, a.w);
}

// ---------------- tiled GEMM with bias (mode 0: xz0 = clip(x) @ Wk0 + b) ----------------
__global__ __launch_bounds__(256) void gemm_bias_kernel(
    const float* __restrict__ Aext,
    const float* __restrict__ W0, const float* __restrict__ W1,
    const float* __restrict__ b0, const float* __restrict__ b1,
    int M, int K)
{
    const int branch = blockIdx.z;
    const float* W = branch ? W1 : W0;
    const float* bias = branch ? b1 : b0;
    const float* A = Aext;
    float* out = g_xz + (size_t)branch * (32u*1024u*1024u);

    __shared__ float As[64][17];
    __shared__ float Bs[16][128];

    const int tid = threadIdx.x;
    const int tr = tid >> 5;
    const int tc = tid & 31;
    const int m0 = blockIdx.y * 64;
    const int n0 = blockIdx.x * 128;

    float acc[8][4];
    #pragma unroll
    for (int i = 0; i < 8; i++)
        #pragma unroll
        for (int j = 0; j < 4; j++) acc[i][j] = 0.f;

    for (int k0 = 0; k0 < K; k0 += 16) {
        #pragma unroll
        for (int i = tid; i < 1024; i += 256) {
            int m = i >> 4, k = i & 15;
            float v = 0.f;
            if (k0 + k < K) {
                v = A[(size_t)(m0 + m) * K + k0 + k];
                v = fminf(3.f, fmaxf(-3.f, v));
            }
            As[m][k] = v;
        }
        #pragma unroll
        for (int i = tid; i < 2048; i += 256) {
            int k = i >> 7, n = i & 127;
            Bs[k][n] = (k0 + k < K) ? W[(size_t)(k0 + k) * 1024 + n0 + n] : 0.f;
        }
        __syncthreads();
        #pragma unroll
        for (int k = 0; k < 16; k++) {
            float4 bv = *(const float4*)&Bs[k][tc * 4];
            #pragma unroll
            for (int i = 0; i < 8; i++) {
                float a = As[tr * 8 + i][k];
                acc[i][0] += a * bv.x;
                acc[i][1] += a * bv.y;
                acc[i][2] += a * bv.z;
                acc[i][3] += a * bv.w;
            }
        }
        __syncthreads();
    }
    float4 bv = *(const float4*)&bias[n0 + tc * 4];
    #pragma unroll
    for (int i = 0; i < 8; i++) {
        float4 r = make_float4(acc[i][0] + bv.x, acc[i][1] + bv.y,
                               acc[i][2] + bv.z, acc[i][3] + bv.w);
        *(float4*)&out[(size_t)(m0 + tr * 8 + i) * 1024 + n0 + tc * 4] = r;
    }
}

// ---------------- 128x128 tiled GEMM with bias (modes 1/2: lstm1 inputs) ----------------
__global__ __launch_bounds__(256) void gemm_bias128_kernel(
    const float* __restrict__ W0, const float* __restrict__ W1,
    const float* __restrict__ b0, const float* __restrict__ b1,
    int mode)
{
    const int branch = blockIdx.z;
    const float* W = branch ? W1 : W0;
    const float* bias = branch ? b1 : b0;
    const float* A = ((mode == 1) ? g_pool : g_hA) + (size_t)branch * (32*342*256);
    float* out = g_xz + (size_t)branch * (32u*342u*1024u);

    __shared__ float As[128][24];   // [m][k], padded
    __shared__ float Bs[16][132];   // [k][n], padded

    const int tid = threadIdx.x;
    const int ty = tid >> 4;
    const int tx = tid & 15;
    const int m0 = blockIdx.y * 128;
    const int n0 = blockIdx.x * 128;

    float acc[8][8];
    #pragma unroll
    for (int i = 0; i < 8; i++)
        #pragma unroll
        for (int j = 0; j < 8; j++) acc[i][j] = 0.f;

    for (int k0 = 0; k0 < 256; k0 += 16) {
        #pragma unroll
        for (int s = tid; s < 512; s += 256) {
            int m = s >> 2, kq = s & 3;
            float4 v = make_float4(0.f, 0.f, 0.f, 0.f);
            if (m0 + m < 10944)
                v = *(const float4*)&A[(size_t)(m0 + m) * 256 + k0 + kq * 4];
            *(float4*)&As[m][kq * 4] = v;
        }
        #pragma unroll
        for (int s = tid; s < 512; s += 256) {
            int k = s >> 5, nq = s & 31;
            *(float4*)&Bs[k][nq * 4] = *(const float4*)&W[(size_t)(k0 + k) * 1024 + n0 + nq * 4];
        }
        __syncthreads();
        #pragma unroll
        for (int k = 0; k < 16; k++) {
            float4 bb0 = *(const float4*)&Bs[k][tx * 4];
            float4 bb1 = *(const float4*)&Bs[k][64 + tx * 4];
            #pragma unroll
            for (int i = 0; i < 8; i++) {
                float a = As[ty * 8 + i][k];
                acc[i][0] = fmaf(a, bb0.x, acc[i][0]);
                acc[i][1] = fmaf(a, bb0.y, acc[i][1]);
                acc[i][2] = fmaf(a, bb0.z, acc[i][2]);
                acc[i][3] = fmaf(a, bb0.w, acc[i][3]);
                acc[i][4] = fmaf(a, bb1.x, acc[i][4]);
                acc[i][5] = fmaf(a, bb1.y, acc[i][5]);
                acc[i][6] = fmaf(a, bb1.z, acc[i][6]);
                acc[i][7] = fmaf(a, bb1.w, acc[i][7]);
            }
        }
        __syncthreads();
    }
    float4 bv0 = *(const float4*)&bias[n0 + tx * 4];
    float4 bv1 = *(const float4*)&bias[n0 + 64 + tx * 4];
    #pragma unroll
    for (int i = 0; i < 8; i++) {
        int m = m0 + ty * 8 + i;
        if (m < 10944) {
            float4 r0 = make_float4(acc[i][0] + bv0.x, acc[i][1] + bv0.y,
                                    acc[i][2] + bv0.z, acc[i][3] + bv0.w);
            float4 r1 = make_float4(acc[i][4] + bv1.x, acc[i][5] + bv1.y,
                                    acc[i][6] + bv1.z, acc[i][7] + bv1.w);
            *(float4*)&out[(size_t)m * 1024 + n0 + tx * 4] = r0;
            *(float4*)&out[(size_t)m * 1024 + n0 + 64 + tx * 4] = r1;
        }
    }
}

// ---------------- persistent recurrent LSTM kernel (8-CTA cluster gangs) ----------------
// Round-9 structure with PER-SOURCE mbarriers: 16 barriers = 2 parities x 8
// source CTAs. Warp kg waits ONLY on barrier (par, kg) — the slice its GEMM
// needs — so early-arriving slices compute while late ones are in flight.
// expect_tx per barrier = 4 batches * 32 units * 4B = 512 B.
// Barrier (par, src) at mbb + (par*8 + src)*8.
__global__ void __launch_bounds__(256, 1) __cluster_dims__(8, 1, 1)
lstm_rec_kernel(
    const float* __restrict__ Wr0, const float* __restrict__ Wr1,
    const int* __restrict__ x_len, int T, int mode)
{
    const int blk = blockIdx.x;
    const int gang = blk >> 3;
    const int cg = blk & 7;
    const int branch = gang >> 3;
    const int bg = gang & 7;
    const int j0 = cg * 32;
    const float* Wr = branch ? Wr1 : Wr0;

    const int tid = threadIdx.x;
    const int kg = tid >> 5;          // warp = k-group 0..7 == source CTA of its slice
    const int lane = tid & 31;
    const int kbase = kg * 32;

    __shared__ __align__(16) float h_s[2][4][256];    // double-buffered h (8KB)
    __shared__ __align__(16) float ps[8][4][128];     // partial sums (16KB)
    __shared__ __align__(8) ull mbar_s[16];

    // ---- mbarrier init + initial expects (idx = par*8 + src) ----
    const uint32_t mbb = smem_u32(&mbar_s[0]);
    if (tid == 0) {
        #pragma unroll
        for (int i = 0; i < 16; i++) mbar_init(mbb + i * 8, 1);
    }
    __syncthreads();
    if (tid == 0) {
        #pragma unroll
        for (int i = 0; i < 16; i++) mbar_expect(mbb + i * 8, 512);
    }

    // ---- zero h(0) buffer ----
    {
        float* p = &h_s[0][0][0];
        #pragma unroll
        for (int i = tid; i < 1024; i += 256) p[i] = 0.f;
    }

    // ---- load weight slice into registers (once): 32 k x 4 cols ----
    float4 wreg[32];
    {
        const int c0 = lane * 4;
        const int gate = c0 >> 5;
        const int jj = c0 & 31;
        const float* wb = Wr + gate * 256 + j0 + jj;
        #pragma unroll
        for (int kk = 0; kk < 32; kk++) {
            const float* wr = wb + (size_t)(kbase + kk) * 1024;
            wreg[kk] = make_float4(wr[0], wr[1], wr[2], wr[3]);
        }
    }

    // ---- gate role (tid < 128): gb = tid>>5, gjj = tid&31 ----
    const int gb = tid >> 5;
    const int gjj = tid & 31;
    const float NEGINF = __int_as_float(0xff800000);
    float cst = 0.f;
    float poolm = NEGINF;
    int mylen = 0;
    const int Tstride = (mode == 0) ? 1024 : 342;
    const float* xzg = nullptr;
    float *poolp = nullptr, *hop = nullptr;
    if (tid < 128) {
        const int b_glob = bg * 4 + gb;
        int xl = x_len[b_glob];
        mylen = (mode == 0) ? xl : (xl + 2) / 3;
        xzg = g_xz + (size_t)branch * 32u * (size_t)Tstride * 1024u
            + (size_t)b_glob * Tstride * 1024u + j0 + gjj;
        poolp = g_pool + ((size_t)(branch * 32 + b_glob) * 342) * 256 + j0 + gjj;
        hop = ((mode == 1) ? g_hA : g_hB) + ((size_t)(branch * 32 + b_glob) * 342) * 256 + j0 + gjj;
    }

    // peer base addresses (8 ranks)
    uint32_t peer_h[8], peer_mb[8];
    {
        const uint32_t hb = smem_u32(&h_s[0][0][0]);
        #pragma unroll
        for (int r = 0; r < 8; r++) {
            peer_h[r] = mapa_rank(hb, r);
            peer_mb[r] = mapa_rank(mbb, r);
        }
    }

    __syncthreads();
    // cluster sync: mbarriers + expects visible before any peer st.async
    asm volatile("barrier.cluster.arrive.aligned;" ::: "memory");
    asm volatile("barrier.cluster.wait.aligned;" ::: "memory");

    uint32_t phase0 = 0, phase1 = 0;     // per-warp parity for its own source barrier

    for (int t = 0; t < T; t++) {
        const int par = t & 1;
        const int par1 = par ^ 1;

        // prefetch xz for this step (gate threads; independent of h)
        float x0, x1, x2, x3;
        if (tid < 128) {
            const float* p = xzg + (size_t)t * 1024;
            x0 = p[0]; x1 = p[256]; x2 = p[512]; x3 = p[768];
        }

        // ---- per-source wait: warp kg waits ONLY for slice kg, then re-arms ----
        if (t > 0) {
            const uint32_t mb = mbb + (uint32_t)((par * 8 + kg) << 3);
            if (par) { mbar_wait(mb, phase1); phase1 ^= 1; }
            else     { mbar_wait(mb, phase0); phase0 ^= 1; }
            if (lane == 0) mbar_expect(mb, 512);
        }

        // ---- GEMM: partial z over owned 32 k rows (slice kg), 4 cols, 4 batches ----
        #pragma unroll
        for (int b = 0; b < 4; b++) {
            float4 acc = make_float4(0.f, 0.f, 0.f, 0.f);
            #pragma unroll
            for (int kk4 = 0; kk4 < 8; kk4++) {
                float4 h4 = *(const float4*)&h_s[par][b][kbase + 4 * kk4];
                fma_bc(acc, h4.x, wreg[4 * kk4 + 0]);
                fma_bc(acc, h4.y, wreg[4 * kk4 + 1]);
                fma_bc(acc, h4.z, wreg[4 * kk4 + 2]);
                fma_bc(acc, h4.w, wreg[4 * kk4 + 3]);
            }
            *(float4*)&ps[kg][b][4 * lane] = acc;
        }
        __syncthreads();

        // ---- gates: fused 8-way reduce + math + packed publish (gate warps) ----
        if (tid < 128) {
            float zi = x0, zf = x1, zg = x2, zo = x3;
            #pragma unroll
            for (int q = 0; q < 8; q++) {
                const float* pp = &ps[q][gb][0];
                zi += pp[gjj];
                zf += pp[32 + gjj];
                zg += pp[64 + gjj];
                zo += pp[96 + gjj];
            }
            float iv = fsigm(zi), fv = fsigm(zf), gv = ftanh_(zg), ov = fsigm(zo);
            float cn = fv * cst + iv * gv;
            float hn = ov * ftanh_(cn);
            bool m = (t < mylen);
            float hp = h_s[par][gb][j0 + gjj];
            float hv = m ? hn : hp;
            cst = m ? cn : cst;

            // pair-pack and send h(t+1) to all 8 cluster CTAs (even lanes, b64)
            // target barrier at each peer: (par1, src = cg)
            float hv_hi = __shfl_down_sync(0xffffffffu, hv, 1);
            if (t + 1 < T && (gjj & 1) == 0) {
                ull hd;
                asm("mov.b64 %0, {%1, %2};" : "=l"(hd) : "f"(hv), "f"(hv_hi));
                const uint32_t off = (uint32_t)(((par1 * 4 + gb) << 8) + j0 + gjj) * 4u;
                const uint32_t moff = (uint32_t)((par1 * 8 + cg) << 3);
                #pragma unroll
                for (int r = 0; r < 8; r++)
                    st_async_b64(peer_h[r] + off, hd, peer_mb[r] + moff);
            }

            // outputs (after sends — off the signal path)
            if (mode == 0) {
                poolm = fmaxf(poolm, hv);
                if ((t % 3) == 1) {
                    poolp[(size_t)(t / 3) * 256] = poolm;
                    poolm = NEGINF;
                }
            } else {
                hop[(size_t)t * 256] = hv;
            }
        }
    }

    // flush final pool window (covers t = 1022,1023)
    if (mode == 0 && tid < 128) {
        poolp[341u * 256] = poolm;
    }
}

// ---------------- CTC projection: out = hB @ ctc_w + ctc_b ----------------
__global__ __launch_bounds__(256) void ctc_kernel(
    const float* __restrict__ W, const float* __restrict__ bias, float* __restrict__ out)
{
    __shared__ float As[8][256];
    const int r0 = blockIdx.x * 8;
    for (int i = threadIdx.x; i < 2048; i += 256) {
        As[i >> 8][i & 255] = g_hB[(size_t)r0 * 256 + i];
    }
    __syncthreads();
    if (threadIdx.x < 240) {
        const int rl = threadIdx.x / 30;
        const int n = threadIdx.x % 30;
        float acc = bias[n];
        #pragma unroll 8
        for (int k = 0; k < 256; k++) acc += As[rl][k] * __ldg(&W[k * 30 + n]);
        const int r = r0 + rl;
        const int branch = r / 10944;
        const int idx = r - branch * 10944;
        const size_t o = (branch ? (size_t)OFF_CTC_C : (size_t)OFF_CTC_S) + (size_t)idx * 30 + n;
        out[o] = acc;
    }
}

// ---------------- lens + close ----------------
__global__ void finalize_kernel(const int* __restrict__ x_len, float* __restrict__ out)
{
    const int b = blockIdx.x;
    const float* s = out + OFF_CTC_S + (size_t)b * 10260;
    const float* c = out + OFF_CTC_C + (size_t)b * 10260;
    int ok = 1;
    for (int i = threadIdx.x; i < 10260; i += 256) {
        if (!(fabsf(s[i] - c[i]) < 1e-5f)) ok = 0;
    }
    int allok = __syncthreads_and(ok);
    if (threadIdx.x == 0) {
        float len = (float)((x_len[b] + 2) / 3);
        out[OFF_LEN_S + b] = len;
        out[OFF_LEN_C + b] = len;
        out[OFF_CLOSE + b] = allok ? 1.f : 0.f;
    }
}

// ---------------- launch ----------------
extern "C" void kernel_launch(void* const* d_in, const int* in_sizes, int n_in,
                              void* d_out, int out_size)
{
    const float* x      = (const float*)d_in[0];
    const int*   x_len  = (const int*)  d_in[1];
    const float* ws0_k  = (const float*)d_in[2];
    const float* ws0_r  = (const float*)d_in[3];
    const float* ws0_b  = (const float*)d_in[4];
    const float* ws1_k  = (const float*)d_in[5];
    const float* ws1_r  = (const float*)d_in[6];
    const float* ws1_b  = (const float*)d_in[7];
    const float* wc0_k  = (const float*)d_in[8];
    const float* wc0_r  = (const float*)d_in[9];
    const float* wc0_b  = (const float*)d_in[10];
    const float* wc1_k  = (const float*)d_in[11];
    const float* wc1_r  = (const float*)d_in[12];
    const float* wc1_b  = (const float*)d_in[13];
    const float* ctc_w  = (const float*)d_in[14];
    const float* ctc_b  = (const float*)d_in[15];
    float* out = (float*)d_out;

    // xz0 = clip(x) @ Wk0 + b0   (M = 32*1024, K = 40)
    gemm_bias_kernel<<<dim3(8, 512, 2), 256>>>(x, ws0_k, wc0_k, ws0_b, wc0_b, 32768, 40);

    // lstm0 + fused maxpool3
    lstm_rec_kernel<<<128, 256>>>(ws0_r, wc0_r, x_len, 1024, 0);

    // xz1A = pooled @ Wk1 + b1   (M = 32*342, K = 256)
    gemm_bias128_kernel<<<dim3(8, 86, 2), 256>>>(ws1_k, wc1_k, ws1_b, wc1_b, 1);

    // lstm1 pass A
    lstm_rec_kernel<<<128, 256>>>(ws1_r, wc1_r, x_len, 342, 1);

    // xz1B = hA @ Wk1 + b1
    gemm_bias128_kernel<<<dim3(8, 86, 2), 256>>>(ws1_k, wc1_k, ws1_b, wc1_b, 2);

    // lstm1 pass B
    lstm_rec_kernel<<<128, 256>>>(ws1_r, wc1_r, x_len, 342, 2);

    // CTC projection for both branches
    ctc_kernel<<<2736, 256>>>(ctc_w, ctc_b, out);

    // lens + close
    finalize_kernel<<<32, 256>>>(x_len, out);
}